// round 9
// baseline (speedup 1.0000x reference)
#include <cuda_runtime.h>
#include <cuda_bf16.h>

// Talking-heads attention via mma.sync bf16 tensor cores (plain sm_100 ISA).
// All GEMMs: bf16 hi/lo split (3 MMAs) -> fp32-class accuracy, fp32 accumulators.
// v8: MMA term-reorder — visit all NI accumulators between dependent split-term
//     MMAs (hh/hl/lh) to break the 3-deep RAW chain on each accumulator.

#define BB 16
#define NN 576
#define CC 768
#define HH 12
#define HDIM 64
#define MTOT (BB * NN)
#define SCALE 0.125f
#define ATT ((size_t)BB * HH * NN * NN)
#define QKE (BB * HH * NN * HDIM)

typedef unsigned int u32;

// ============================ PTX helpers (sm_80+ ISA only) ============================
__device__ __forceinline__ u32 smem_u32(const void* p) {
    u32 a;
    asm("{ .reg .u64 t; cvta.to.shared.u64 t, %1; cvt.u32.u64 %0, t; }" : "=r"(a) : "l"(p));
    return a;
}
__device__ __forceinline__ void cp16(u32 dst, const void* src) {
    asm volatile("cp.async.cg.shared.global [%0], [%1], 16;" :: "r"(dst), "l"(src));
}
__device__ __forceinline__ void cp_commit() {
    asm volatile("cp.async.commit_group;" ::: "memory");
}
template <int N>
__device__ __forceinline__ void cp_wait() {
    asm volatile("cp.async.wait_group %0;" :: "n"(N) : "memory");
}
__device__ __forceinline__ void ldm_x4(u32 a, u32& r0, u32& r1, u32& r2, u32& r3) {
    asm volatile("ldmatrix.sync.aligned.m8n8.x4.shared.b16 {%0,%1,%2,%3}, [%4];"
                 : "=r"(r0), "=r"(r1), "=r"(r2), "=r"(r3) : "r"(a));
}
__device__ __forceinline__ void mma_bf16(float* d, const u32* a, const u32* b) {
    asm volatile("mma.sync.aligned.m16n8k16.row.col.f32.bf16.bf16.f32 "
                 "{%0,%1,%2,%3}, {%4,%5,%6,%7}, {%8,%9}, {%0,%1,%2,%3};"
                 : "+f"(d[0]), "+f"(d[1]), "+f"(d[2]), "+f"(d[3])
                 : "r"(a[0]), "r"(a[1]), "r"(a[2]), "r"(a[3]), "r"(b[0]), "r"(b[1]));
}

// ============================ scratch (16B-aligned) ============================
__device__ __align__(16) __nv_bfloat16 g_xh[MTOT * CC], g_xl[MTOT * CC];
__device__ __align__(16) __nv_bfloat16 g_wqh[3 * CC * CC], g_wql[3 * CC * CC];
__device__ __align__(16) __nv_bfloat16 g_wph[CC * CC], g_wpl[CC * CC];
__device__ __align__(16) __nv_bfloat16 g_qh[QKE + 64 * HDIM], g_ql[QKE + 64 * HDIM];
__device__ __align__(16) __nv_bfloat16 g_kh[QKE + 64 * HDIM], g_kl[QKE + 64 * HDIM];
__device__ __align__(16) __nv_bfloat16 g_vh[QKE], g_vl[QKE];
__device__ __align__(16) __nv_bfloat16 g_vth[QKE], g_vtl[QKE];
__device__ __align__(16) float g_attn[ATT];
__device__ __align__(16) __nv_bfloat16 g_a2h[ATT + 64 * NN], g_a2l[ATT + 64 * NN];
__device__ __align__(16) __nv_bfloat16 g_o1h[MTOT * CC], g_o1l[MTOT * CC];

__device__ __forceinline__ u32 pack_hi_lo(float f0, float f1, u32& lo_out) {
    __nv_bfloat16 h0 = __float2bfloat16(f0);
    __nv_bfloat16 h1 = __float2bfloat16(f1);
    __nv_bfloat16 l0 = __float2bfloat16(f0 - __bfloat162float(h0));
    __nv_bfloat16 l1 = __float2bfloat16(f1 - __bfloat162float(h1));
    u32 hw = ((u32)__bfloat16_as_ushort(h1) << 16) | __bfloat16_as_ushort(h0);
    lo_out = ((u32)__bfloat16_as_ushort(l1) << 16) | __bfloat16_as_ushort(l0);
    return hw;
}

// ============================ core GEMM mainloop (3-stage pipeline) ============================
// C[m,n] = sum_k A[m,k]*B[n,k]; BM x BN tile, BK=32, 256 threads, TMW x TNW warps.
// v8: per-acc split terms separated by NI independent MMAs (same per-acc order ->
//     numerics identical to v7).
template <int BM, int BN, int TMW, int TNW>
__device__ __forceinline__ void gemm_core(
    const __nv_bfloat16* __restrict__ Ah, const __nv_bfloat16* __restrict__ Al, int lda,
    const __nv_bfloat16* __restrict__ Bh, const __nv_bfloat16* __restrict__ Bl, int ldb,
    int K, u32 sb, float (*acc)[4][4]) {
    constexpr int MI = BM / TMW / 16;
    constexpr int NI = BN / TNW / 8;
    static_assert(NI == 4, "epilogue layout assumes NI==4");
    constexpr u32 OFF_AL = BM * 64;
    constexpr u32 OFF_BH = 2 * BM * 64;
    constexpr u32 OFF_BL = 2 * BM * 64 + BN * 64;
    constexpr u32 SS = (2 * BM + 2 * BN) * 64;
    const int tid = threadIdx.x;
    const int lane = tid & 31, wid = tid >> 5;
    const int wrow = (wid / TNW) * (BM / TMW);
    const int wcol = (wid % TNW) * (BN / TNW);
    const int NK = K >> 5;

    auto issue = [&](int kt) {
        const u32 st = sb + (u32)(kt % 3) * SS;
        const int k0 = kt << 5;
#pragma unroll
        for (int i = tid; i < BM * 4; i += 256) {
            int r = i >> 2, c = i & 3;
            u32 doff = (u32)(r * 64 + ((c ^ ((r >> 1) & 3)) << 4));
            cp16(st + doff, Ah + (size_t)r * lda + k0 + c * 8);
            cp16(st + OFF_AL + doff, Al + (size_t)r * lda + k0 + c * 8);
        }
#pragma unroll
        for (int i = tid; i < BN * 4; i += 256) {
            int r = i >> 2, c = i & 3;
            u32 doff = (u32)(r * 64 + ((c ^ ((r >> 1) & 3)) << 4));
            cp16(st + OFF_BH + doff, Bh + (size_t)r * ldb + k0 + c * 8);
            cp16(st + OFF_BL + doff, Bl + (size_t)r * ldb + k0 + c * 8);
        }
        cp_commit();
    };

    issue(0);
    if (NK > 1) issue(1);
    for (int kt = 0; kt < NK; kt++) {
        if (kt + 1 < NK) cp_wait<1>();
        else             cp_wait<0>();
        __syncthreads();
        if (kt + 2 < NK) issue(kt + 2);
        const u32 st = sb + (u32)(kt % 3) * SS;
#pragma unroll
        for (int ks = 0; ks < 2; ks++) {
            u32 bhf[NI][2], blf[NI][2];
            {
                const int kc = ks * 2 + ((lane >> 3) & 1);
                const int rb = wcol + ((lane >> 4) << 3) + (lane & 7);
#pragma unroll
                for (int ni = 0; ni < NI; ni += 2) {
                    int r = rb + ni * 8;
                    u32 swz = (u32)(r * 64 + ((kc ^ ((r >> 1) & 3)) << 4));
                    ldm_x4(st + OFF_BH + swz, bhf[ni][0], bhf[ni][1], bhf[ni + 1][0], bhf[ni + 1][1]);
                    ldm_x4(st + OFF_BL + swz, blf[ni][0], blf[ni][1], blf[ni + 1][0], blf[ni + 1][1]);
                }
            }
            const int kcA = ks * 2 + (lane >> 4);
#pragma unroll
            for (int mi = 0; mi < MI; mi++) {
                int r = wrow + mi * 16 + (lane & 15);
                u32 a = st + (u32)(r * 64 + ((kcA ^ ((r >> 1) & 3)) << 4));
                u32 ahf[4], alf[4];
                ldm_x4(a, ahf[0], ahf[1], ahf[2], ahf[3]);
                ldm_x4(a + OFF_AL, alf[0], alf[1], alf[2], alf[3]);
                // term-major order: all NI accs between dependent MMAs on one acc
#pragma unroll
                for (int ni = 0; ni < NI; ni++) mma_bf16(acc[mi][ni], ahf, bhf[ni]);  // hi*hi
#pragma unroll
                for (int ni = 0; ni < NI; ni++) mma_bf16(acc[mi][ni], ahf, blf[ni]);  // hi*lo
#pragma unroll
                for (int ni = 0; ni < NI; ni++) mma_bf16(acc[mi][ni], alf, bhf[ni]);  // lo*hi
            }
        }
    }
}

#define GEMM_SMEM_BIG 98304   // 3 stages x 32768 (BM=128,BN=128)
#define GEMM_SMEM_AV  73728   // 3 stages x 24576 (BM=128,BN=64)
#define SCORE_SMEM    81920   // A 32768 + 3 stages x 16384

// ============================ fp32 -> bf16 hi/lo split ============================
__global__ __launch_bounds__(256) void split_kernel(const float* __restrict__ in,
                                                    __nv_bfloat16* __restrict__ hi,
                                                    __nv_bfloat16* __restrict__ lo, int n) {
    int i = (blockIdx.x * 256 + threadIdx.x) * 4;
    if (i >= n) return;
    float4 v = *reinterpret_cast<const float4*>(in + i);
    u32 l0, l1;
    u32 h0 = pack_hi_lo(v.x, v.y, l0);
    u32 h1 = pack_hi_lo(v.z, v.w, l1);
    *reinterpret_cast<uint2*>(hi + i) = make_uint2(h0, h1);
    *reinterpret_cast<uint2*>(lo + i) = make_uint2(l0, l1);
}

// ============================ QKV GEMM + scatter (BN=128) ============================
// grid (2304/128=18, 9216/128=72)
__global__ __launch_bounds__(256, 2) void qkv_mma() {
    extern __shared__ char smem[];
    u32 sb = smem_u32(smem);
    const int n0 = blockIdx.x * 128, m0 = blockIdx.y * 128;
    float acc[4][4][4];
#pragma unroll
    for (int i = 0; i < 4; i++)
#pragma unroll
        for (int j = 0; j < 4; j++)
#pragma unroll
            for (int k = 0; k < 4; k++) acc[i][j][k] = 0.f;
    gemm_core<128, 128, 2, 4>(g_xh + (size_t)m0 * CC, g_xl + (size_t)m0 * CC, CC,
                              g_wqh + (size_t)n0 * CC, g_wql + (size_t)n0 * CC, CC,
                              CC, sb, acc);
    const int tid = threadIdx.x, lane = tid & 31, wid = tid >> 5;
    const int wm = wid >> 2, wn = wid & 3;
#pragma unroll
    for (int mi = 0; mi < 4; mi++)
#pragma unroll
        for (int ni = 0; ni < 4; ni++) {
            int c = n0 + wn * 32 + ni * 8 + (lane & 3) * 2;
            int t = c / CC, rc = c - t * CC, h = rc >> 6, d0 = rc & 63;
            float sc = (t == 0) ? SCALE : 1.f;
            __nv_bfloat16* ph = (t == 0) ? g_qh : (t == 1) ? g_kh : g_vh;
            __nv_bfloat16* pl = (t == 0) ? g_ql : (t == 1) ? g_kl : g_vl;
#pragma unroll
            for (int hf = 0; hf < 2; hf++) {
                int m = m0 + wm * 64 + mi * 16 + (lane >> 2) + hf * 8;
                int b = m / NN, ntok = m - b * NN;
                size_t base = ((size_t)(b * HH + h) * NN + ntok) * HDIM + d0;
                u32 lw, hw = pack_hi_lo(acc[mi][ni][hf * 2] * sc, acc[mi][ni][hf * 2 + 1] * sc, lw);
                *reinterpret_cast<u32*>(ph + base) = hw;
                *reinterpret_cast<u32*>(pl + base) = lw;
            }
        }
}

// ============================ transpose V -> vT[d][n] ============================
__global__ __launch_bounds__(256) void transpose_v() {
    __shared__ __nv_bfloat16 th[32][33], tl[32][33];
    int n0 = blockIdx.x * 32, d0 = blockIdx.y * 32, bh = blockIdx.z;
    int tx = threadIdx.x, ty = threadIdx.y;
#pragma unroll
    for (int i = 0; i < 4; i++) {
        int n = n0 + ty + i * 8;
        size_t s = ((size_t)bh * NN + n) * HDIM + d0 + tx;
        th[ty + i * 8][tx] = g_vh[s];
        tl[ty + i * 8][tx] = g_vl[s];
    }
    __syncthreads();
#pragma unroll
    for (int i = 0; i < 4; i++) {
        int d = d0 + ty + i * 8;
        size_t t = ((size_t)bh * HDIM + d) * NN + n0 + tx;
        g_vth[t] = th[tx][ty + i * 8];
        g_vtl[t] = tl[tx][ty + i * 8];
    }
}

// ============================ score: persistent-Q n-loop kernel ============================
// grid (5, 192). Q tile resident; K tiles stream through a 3-stage ring.
__global__ __launch_bounds__(256) void score_mma() {
    extern __shared__ char smem[];
    u32 sb = smem_u32(smem);
    const u32 A_HI = 0, A_LO = 16384, RING = 32768;
    const int m0 = blockIdx.x * 128, bhi = blockIdx.y;
    const int tid = threadIdx.x, lane = tid & 31, wid = tid >> 5;
    const int wm = wid >> 1, wn = wid & 1;
    const int wrow = wm * 32, wcol = wn * 32;

    const __nv_bfloat16* Qh = g_qh + ((size_t)bhi * NN + m0) * HDIM;
    const __nv_bfloat16* Ql = g_ql + ((size_t)bhi * NN + m0) * HDIM;
    const __nv_bfloat16* Kh = g_kh + (size_t)bhi * NN * HDIM;
    const __nv_bfloat16* Kl = g_kl + (size_t)bhi * NN * HDIM;

#pragma unroll
    for (int i = tid; i < 128 * 8; i += 256) {
        int r = i >> 3, cc = i & 7, kt = cc >> 2, c = cc & 3;
        u32 doff = (u32)(kt * 8192 + r * 64 + ((c ^ ((r >> 1) & 3)) << 4));
        size_t so = (size_t)r * HDIM + kt * 32 + c * 8;
        cp16(sb + A_HI + doff, Qh + so);
        cp16(sb + A_LO + doff, Ql + so);
    }
    cp_commit();

    auto issueB = [&](int nt) {
        const u32 st = sb + RING + (u32)(nt % 3) * 16384;
#pragma unroll
        for (int i = tid; i < 64 * 8; i += 256) {
            int r = i >> 3, cc = i & 7, kt = cc >> 2, c = cc & 3;
            u32 doff = (u32)(kt * 4096 + r * 64 + ((c ^ ((r >> 1) & 3)) << 4));
            size_t so = (size_t)(nt * 64 + r) * HDIM + kt * 32 + c * 8;
            cp16(st + doff, Kh + so);
            cp16(st + 8192 + doff, Kl + so);
        }
        cp_commit();
    };
    issueB(0); issueB(1);

    float* outb = g_attn + (size_t)bhi * NN * NN;
    for (int nt = 0; nt < 9; nt++) {
        if (nt < 8) cp_wait<1>();
        else        cp_wait<0>();
        __syncthreads();
        if (nt + 2 < 9) issueB(nt + 2);
        const u32 st = sb + RING + (u32)(nt % 3) * 16384;

        float acc[2][4][4];
#pragma unroll
        for (int i = 0; i < 2; i++)
#pragma unroll
            for (int j = 0; j < 4; j++)
#pragma unroll
                for (int k = 0; k < 4; k++) acc[i][j][k] = 0.f;

#pragma unroll
        for (int kt = 0; kt < 2; kt++)
#pragma unroll
            for (int ks = 0; ks < 2; ks++) {
                u32 bhf[4][2], blf[4][2];
                {
                    const int kc = ks * 2 + ((lane >> 3) & 1);
                    const int rb = wcol + ((lane >> 4) << 3) + (lane & 7);
#pragma unroll
                    for (int ni = 0; ni < 4; ni += 2) {
                        int r = rb + ni * 8;
                        u32 swz = (u32)(kt * 4096 + r * 64 + ((kc ^ ((r >> 1) & 3)) << 4));
                        ldm_x4(st + swz, bhf[ni][0], bhf[ni][1], bhf[ni + 1][0], bhf[ni + 1][1]);
                        ldm_x4(st + 8192 + swz, blf[ni][0], blf[ni][1], blf[ni + 1][0], blf[ni + 1][1]);
                    }
                }
                const int kcA = ks * 2 + (lane >> 4);
#pragma unroll
                for (int mi = 0; mi < 2; mi++) {
                    int r = wrow + mi * 16 + (lane & 15);
                    u32 aoff = (u32)(kt * 8192 + r * 64 + ((kcA ^ ((r >> 1) & 3)) << 4));
                    u32 ahf[4], alf[4];
                    ldm_x4(sb + A_HI + aoff, ahf[0], ahf[1], ahf[2], ahf[3]);
                    ldm_x4(sb + A_LO + aoff, alf[0], alf[1], alf[2], alf[3]);
#pragma unroll
                    for (int ni = 0; ni < 4; ni++) mma_bf16(acc[mi][ni], ahf, bhf[ni]);
#pragma unroll
                    for (int ni = 0; ni < 4; ni++) mma_bf16(acc[mi][ni], ahf, blf[ni]);
#pragma unroll
                    for (int ni = 0; ni < 4; ni++) mma_bf16(acc[mi][ni], alf, bhf[ni]);
                }
            }

        const int n0 = nt * 64;
#pragma unroll
        for (int mi = 0; mi < 2; mi++)
#pragma unroll
            for (int ni = 0; ni < 4; ni++) {
                int c = n0 + wn * 32 + ni * 8 + (lane & 3) * 2;
#pragma unroll
                for (int hf = 0; hf < 2; hf++) {
                    int m = m0 + wm * 32 + mi * 16 + (lane >> 2) + hf * 8;
                    if (m < NN)
                        *reinterpret_cast<float2*>(outb + (size_t)m * NN + c) =
                            make_float2(acc[mi][ni][hf * 2], acc[mi][ni][hf * 2 + 1]);
                }
            }
    }
}

// ============================ softmax + both talking-heads mixes ============================
__global__ __launch_bounds__(384) void softmax_mix_kernel(const float* __restrict__ Wl,
                                                          const float* __restrict__ bl,
                                                          const float* __restrict__ Ww,
                                                          const float* __restrict__ bw) {
    __shared__ __align__(16) float sm[HH][NN];
    __shared__ float wls[HH * HH], bls[HH], wws[HH * HH], bws[HH];
    const int bm = blockIdx.x;
    const int b = bm / NN, m = bm % NN;
    const int tid = threadIdx.x, lane = tid & 31, wid = tid >> 5;

    if (tid < HH * HH) { wls[tid] = Wl[tid]; wws[tid] = Ww[tid]; }
    if (tid < HH) { bls[tid] = bl[tid]; bws[tid] = bw[tid]; }

    for (int idx = tid; idx < HH * NN / 4; idx += 384) {
        int h = idx / (NN / 4), n4 = idx - h * (NN / 4);
        float4 v = *reinterpret_cast<const float4*>(
            &g_attn[((size_t)(b * HH + h) * NN + m) * NN + n4 * 4]);
        *reinterpret_cast<float4*>(&sm[h][n4 * 4]) = v;
    }
    __syncthreads();

    for (int n = tid; n < NN; n += 384) {
        float p[HH];
#pragma unroll
        for (int h = 0; h < HH; h++) p[h] = sm[h][n];
#pragma unroll
        for (int g = 0; g < HH; g++) {
            float o = bls[g];
#pragma unroll
            for (int h = 0; h < HH; h++) o += wls[g * HH + h] * p[h];
            sm[g][n] = o;
        }
    }
    __syncthreads();

    {
        const int h = wid;
        float mx = -1e30f;
        for (int n = lane; n < NN; n += 32) mx = fmaxf(mx, sm[h][n]);
#pragma unroll
        for (int o = 16; o > 0; o >>= 1) mx = fmaxf(mx, __shfl_xor_sync(0xffffffffu, mx, o));
        float sum = 0.f;
        for (int n = lane; n < NN; n += 32) {
            float e = __expf(sm[h][n] - mx);
            sm[h][n] = e; sum += e;
        }
#pragma unroll
        for (int o = 16; o > 0; o >>= 1) sum += __shfl_xor_sync(0xffffffffu, sum, o);
        float inv = 1.f / sum;
        for (int n = lane; n < NN; n += 32) sm[h][n] *= inv;
    }
    __syncthreads();

    for (int n2 = tid; n2 < NN / 2; n2 += 384) {
        int n = n2 * 2;
        float p0[HH], p1[HH];
#pragma unroll
        for (int h = 0; h < HH; h++) { p0[h] = sm[h][n]; p1[h] = sm[h][n + 1]; }
#pragma unroll
        for (int g = 0; g < HH; g++) {
            float o0 = bws[g], o1 = bws[g];
#pragma unroll
            for (int h = 0; h < HH; h++) { o0 += wws[g * HH + h] * p0[h]; o1 += wws[g * HH + h] * p1[h]; }
            size_t idx = ((size_t)(b * HH + g) * NN + m) * NN + n;
            u32 lw, hw = pack_hi_lo(o0, o1, lw);
            *reinterpret_cast<u32*>(g_a2h + idx) = hw;
            *reinterpret_cast<u32*>(g_a2l + idx) = lw;
        }
    }
}

// ============================ O = attn2 @ V per (b,h) ============================
// grid (5, 192). K = 576.
__global__ __launch_bounds__(256) void av_mma() {
    extern __shared__ char smem[];
    u32 sb = smem_u32(smem);
    const int m0 = blockIdx.x * 128, bh = blockIdx.y;
    float acc[2][4][4];
#pragma unroll
    for (int i = 0; i < 2; i++)
#pragma unroll
        for (int j = 0; j < 4; j++)
#pragma unroll
            for (int k = 0; k < 4; k++) acc[i][j][k] = 0.f;
    const size_t ab = (size_t)bh * NN * NN + (size_t)m0 * NN;
    const size_t bb = (size_t)bh * HDIM * NN;
    gemm_core<128, 64, 4, 2>(g_a2h + ab, g_a2l + ab, NN,
                             g_vth + bb, g_vtl + bb, NN, NN, sb, acc);
    const int tid = threadIdx.x, lane = tid & 31, wid = tid >> 5;
    const int wm = wid >> 1, wn = wid & 1;
    const int b = bh / HH, h = bh - b * HH;
#pragma unroll
    for (int mi = 0; mi < 2; mi++)
#pragma unroll
        for (int ni = 0; ni < 4; ni++) {
            int dc = wn * 32 + ni * 8 + (lane & 3) * 2;
#pragma unroll
            for (int hf = 0; hf < 2; hf++) {
                int m = m0 + wm * 32 + mi * 16 + (lane >> 2) + hf * 8;
                if (m < NN) {
                    size_t base = ((size_t)b * NN + m) * CC + h * HDIM + dc;
                    u32 lw, hw = pack_hi_lo(acc[mi][ni][hf * 2], acc[mi][ni][hf * 2 + 1], lw);
                    *reinterpret_cast<u32*>(g_o1h + base) = hw;
                    *reinterpret_cast<u32*>(g_o1l + base) = lw;
                }
            }
        }
}

// ============================ out = o1 @ Wproj^T + bias (BN=128) ============================
// grid (6, 72)
__global__ __launch_bounds__(256, 2) void proj_mma(const float* __restrict__ bias,
                                                   float* __restrict__ out) {
    extern __shared__ char smem[];
    u32 sb = smem_u32(smem);
    const int n0 = blockIdx.x * 128, m0 = blockIdx.y * 128;
    float acc[4][4][4];
#pragma unroll
    for (int i = 0; i < 4; i++)
#pragma unroll
        for (int j = 0; j < 4; j++)
#pragma unroll
            for (int k = 0; k < 4; k++) acc[i][j][k] = 0.f;
    gemm_core<128, 128, 2, 4>(g_o1h + (size_t)m0 * CC, g_o1l + (size_t)m0 * CC, CC,
                              g_wph + (size_t)n0 * CC, g_wpl + (size_t)n0 * CC, CC,
                              CC, sb, acc);
    const int tid = threadIdx.x, lane = tid & 31, wid = tid >> 5;
    const int wm = wid >> 2, wn = wid & 3;
#pragma unroll
    for (int mi = 0; mi < 4; mi++)
#pragma unroll
        for (int ni = 0; ni < 4; ni++) {
            int c = n0 + wn * 32 + ni * 8 + (lane & 3) * 2;
            float b0 = __ldg(&bias[c]), b1 = __ldg(&bias[c + 1]);
#pragma unroll
            for (int hf = 0; hf < 2; hf++) {
                int m = m0 + wm * 64 + mi * 16 + (lane >> 2) + hf * 8;
                *reinterpret_cast<float2*>(out + (size_t)m * CC + c) =
                    make_float2(acc[mi][ni][hf * 2] + b0, acc[mi][ni][hf * 2 + 1] + b1);
            }
        }
}

// ============================ launch ============================
extern "C" void kernel_launch(void* const* d_in, const int* in_sizes, int n_in,
                              void* d_out, int out_size) {
    const float* x     = (const float*)d_in[0];
    const float* Wqkv  = (const float*)d_in[1];
    const float* Wl    = (const float*)d_in[2];
    const float* bl    = (const float*)d_in[3];
    const float* Ww    = (const float*)d_in[4];
    const float* bw    = (const float*)d_in[5];
    const float* Wproj = (const float*)d_in[6];
    const float* bproj = (const float*)d_in[7];
    float* out = (float*)d_out;

    static bool attr_done = false;
    if (!attr_done) {
        cudaFuncSetAttribute(qkv_mma,   cudaFuncAttributeMaxDynamicSharedMemorySize, GEMM_SMEM_BIG);
        cudaFuncSetAttribute(score_mma, cudaFuncAttributeMaxDynamicSharedMemorySize, SCORE_SMEM);
        cudaFuncSetAttribute(av_mma,    cudaFuncAttributeMaxDynamicSharedMemorySize, GEMM_SMEM_AV);
        cudaFuncSetAttribute(proj_mma,  cudaFuncAttributeMaxDynamicSharedMemorySize, GEMM_SMEM_BIG);
        attr_done = true;
    }

    __nv_bfloat16 *xh, *xl, *wqh, *wql, *wph, *wpl;
    cudaGetSymbolAddress((void**)&xh, g_xh);   cudaGetSymbolAddress((void**)&xl, g_xl);
    cudaGetSymbolAddress((void**)&wqh, g_wqh); cudaGetSymbolAddress((void**)&wql, g_wql);
    cudaGetSymbolAddress((void**)&wph, g_wph); cudaGetSymbolAddress((void**)&wpl, g_wpl);

    split_kernel<<<(MTOT * CC / 4 + 255) / 256, 256>>>(x, xh, xl, MTOT * CC);
    split_kernel<<<(3 * CC * CC / 4 + 255) / 256, 256>>>(Wqkv, wqh, wql, 3 * CC * CC);
    split_kernel<<<(CC * CC / 4 + 255) / 256, 256>>>(Wproj, wph, wpl, CC * CC);

    qkv_mma<<<dim3(18, 72), 256, GEMM_SMEM_BIG>>>();
    transpose_v<<<dim3(18, 2, BB * HH), dim3(32, 8)>>>();
    score_mma<<<dim3(5, BB * HH), 256, SCORE_SMEM>>>();
    softmax_mix_kernel<<<MTOT, 384>>>(Wl, bl, Ww, bw);
    av_mma<<<dim3(5, BB * HH), 256, GEMM_SMEM_AV>>>();
    proj_mma<<<dim3(6, 72), 256, GEMM_SMEM_BIG>>>(bproj, out);
}

// round 10
// speedup vs baseline: 1.0908x; 1.0908x over previous
#include <cuda_runtime.h>
#include <cuda_bf16.h>
#include <cuda_fp16.h>

// Talking-heads attention via mma.sync tensor cores (plain sm_100 ISA).
// v10: precision-budget arbitrage — attn2 & o1 stored as single fp16, so
//      av & proj GEMMs run 2 MMAs/k-step (A_f16 x Bhi + A_f16 x Blo).
//      qkv & score remain bf16 hi/lo 3-term.

#define BB 16
#define NN 576
#define CC 768
#define HH 12
#define HDIM 64
#define MTOT (BB * NN)
#define SCALE 0.125f
#define ATT ((size_t)BB * HH * NN * NN)
#define QKE (BB * HH * NN * HDIM)

typedef unsigned int u32;

// ============================ PTX helpers ============================
__device__ __forceinline__ u32 smem_u32(const void* p) {
    u32 a;
    asm("{ .reg .u64 t; cvta.to.shared.u64 t, %1; cvt.u32.u64 %0, t; }" : "=r"(a) : "l"(p));
    return a;
}
__device__ __forceinline__ void cp16(u32 dst, const void* src) {
    asm volatile("cp.async.cg.shared.global [%0], [%1], 16;" :: "r"(dst), "l"(src));
}
__device__ __forceinline__ void cp_commit() {
    asm volatile("cp.async.commit_group;" ::: "memory");
}
template <int N>
__device__ __forceinline__ void cp_wait() {
    asm volatile("cp.async.wait_group %0;" :: "n"(N) : "memory");
}
__device__ __forceinline__ void ldm_x4(u32 a, u32& r0, u32& r1, u32& r2, u32& r3) {
    asm volatile("ldmatrix.sync.aligned.m8n8.x4.shared.b16 {%0,%1,%2,%3}, [%4];"
                 : "=r"(r0), "=r"(r1), "=r"(r2), "=r"(r3) : "r"(a));
}
__device__ __forceinline__ void mma_bf16(float* d, const u32* a, const u32* b) {
    asm volatile("mma.sync.aligned.m16n8k16.row.col.f32.bf16.bf16.f32 "
                 "{%0,%1,%2,%3}, {%4,%5,%6,%7}, {%8,%9}, {%0,%1,%2,%3};"
                 : "+f"(d[0]), "+f"(d[1]), "+f"(d[2]), "+f"(d[3])
                 : "r"(a[0]), "r"(a[1]), "r"(a[2]), "r"(a[3]), "r"(b[0]), "r"(b[1]));
}
__device__ __forceinline__ void mma_f16(float* d, const u32* a, const u32* b) {
    asm volatile("mma.sync.aligned.m16n8k16.row.col.f32.f16.f16.f32 "
                 "{%0,%1,%2,%3}, {%4,%5,%6,%7}, {%8,%9}, {%0,%1,%2,%3};"
                 : "+f"(d[0]), "+f"(d[1]), "+f"(d[2]), "+f"(d[3])
                 : "r"(a[0]), "r"(a[1]), "r"(a[2]), "r"(a[3]), "r"(b[0]), "r"(b[1]));
}

// ============================ scratch (16B-aligned) ============================
__device__ __align__(16) __nv_bfloat16 g_xh[MTOT * CC], g_xl[MTOT * CC];
__device__ __align__(16) __nv_bfloat16 g_wqh[3 * CC * CC], g_wql[3 * CC * CC];
__device__ __align__(16) __nv_bfloat16 g_qh[QKE + 64 * HDIM], g_ql[QKE + 64 * HDIM];
__device__ __align__(16) __nv_bfloat16 g_kh[QKE + 64 * HDIM], g_kl[QKE + 64 * HDIM];
__device__ __align__(16) __nv_bfloat16 g_vh[QKE], g_vl[QKE];
__device__ __align__(16) float g_attn[ATT];
// fp16 path (av / proj)
__device__ __align__(16) __half g_vthf[QKE], g_vtlf[QKE];        // V^T fp16 hi/lo
__device__ __align__(16) __half g_a2f[ATT + 64 * NN];            // attn2 single fp16
__device__ __align__(16) __half g_o1f[MTOT * CC];                // o1 single fp16
__device__ __align__(16) __half g_wphf[CC * CC], g_wplf[CC * CC];// Wproj fp16 hi/lo

__device__ __forceinline__ u32 pack_hi_lo(float f0, float f1, u32& lo_out) {
    __nv_bfloat16 h0 = __float2bfloat16(f0);
    __nv_bfloat16 h1 = __float2bfloat16(f1);
    __nv_bfloat16 l0 = __float2bfloat16(f0 - __bfloat162float(h0));
    __nv_bfloat16 l1 = __float2bfloat16(f1 - __bfloat162float(h1));
    u32 hw = ((u32)__bfloat16_as_ushort(h1) << 16) | __bfloat16_as_ushort(h0);
    lo_out = ((u32)__bfloat16_as_ushort(l1) << 16) | __bfloat16_as_ushort(l0);
    return hw;
}

// ============================ bf16 pair/pair GEMM core (3-stage, 3-MMA) ============================
template <int BM, int BN, int TMW, int TNW>
__device__ __forceinline__ void gemm_core(
    const __nv_bfloat16* __restrict__ Ah, const __nv_bfloat16* __restrict__ Al, int lda,
    const __nv_bfloat16* __restrict__ Bh, const __nv_bfloat16* __restrict__ Bl, int ldb,
    int K, u32 sb, float (*acc)[4][4]) {
    constexpr int MI = BM / TMW / 16;
    constexpr int NI = BN / TNW / 8;
    static_assert(NI == 4, "epilogue layout assumes NI==4");
    constexpr u32 OFF_AL = BM * 64;
    constexpr u32 OFF_BH = 2 * BM * 64;
    constexpr u32 OFF_BL = 2 * BM * 64 + BN * 64;
    constexpr u32 SS = (2 * BM + 2 * BN) * 64;
    const int tid = threadIdx.x;
    const int lane = tid & 31, wid = tid >> 5;
    const int wrow = (wid / TNW) * (BM / TMW);
    const int wcol = (wid % TNW) * (BN / TNW);
    const int NK = K >> 5;

    auto issue = [&](int kt) {
        const u32 st = sb + (u32)(kt % 3) * SS;
        const int k0 = kt << 5;
#pragma unroll
        for (int i = tid; i < BM * 4; i += 256) {
            int r = i >> 2, c = i & 3;
            u32 doff = (u32)(r * 64 + ((c ^ ((r >> 1) & 3)) << 4));
            cp16(st + doff, Ah + (size_t)r * lda + k0 + c * 8);
            cp16(st + OFF_AL + doff, Al + (size_t)r * lda + k0 + c * 8);
        }
#pragma unroll
        for (int i = tid; i < BN * 4; i += 256) {
            int r = i >> 2, c = i & 3;
            u32 doff = (u32)(r * 64 + ((c ^ ((r >> 1) & 3)) << 4));
            cp16(st + OFF_BH + doff, Bh + (size_t)r * ldb + k0 + c * 8);
            cp16(st + OFF_BL + doff, Bl + (size_t)r * ldb + k0 + c * 8);
        }
        cp_commit();
    };

    issue(0);
    if (NK > 1) issue(1);
    for (int kt = 0; kt < NK; kt++) {
        if (kt + 1 < NK) cp_wait<1>();
        else             cp_wait<0>();
        __syncthreads();
        if (kt + 2 < NK) issue(kt + 2);
        const u32 st = sb + (u32)(kt % 3) * SS;
#pragma unroll
        for (int ks = 0; ks < 2; ks++) {
            u32 bhf[NI][2], blf[NI][2];
            {
                const int kc = ks * 2 + ((lane >> 3) & 1);
                const int rb = wcol + ((lane >> 4) << 3) + (lane & 7);
#pragma unroll
                for (int ni = 0; ni < NI; ni += 2) {
                    int r = rb + ni * 8;
                    u32 swz = (u32)(r * 64 + ((kc ^ ((r >> 1) & 3)) << 4));
                    ldm_x4(st + OFF_BH + swz, bhf[ni][0], bhf[ni][1], bhf[ni + 1][0], bhf[ni + 1][1]);
                    ldm_x4(st + OFF_BL + swz, blf[ni][0], blf[ni][1], blf[ni + 1][0], blf[ni + 1][1]);
                }
            }
            const int kcA = ks * 2 + (lane >> 4);
#pragma unroll
            for (int mi = 0; mi < MI; mi++) {
                int r = wrow + mi * 16 + (lane & 15);
                u32 a = st + (u32)(r * 64 + ((kcA ^ ((r >> 1) & 3)) << 4));
                u32 ahf[4], alf[4];
                ldm_x4(a, ahf[0], ahf[1], ahf[2], ahf[3]);
                ldm_x4(a + OFF_AL, alf[0], alf[1], alf[2], alf[3]);
#pragma unroll
                for (int ni = 0; ni < NI; ni++) mma_bf16(acc[mi][ni], ahf, bhf[ni]);
#pragma unroll
                for (int ni = 0; ni < NI; ni++) mma_bf16(acc[mi][ni], ahf, blf[ni]);
#pragma unroll
                for (int ni = 0; ni < NI; ni++) mma_bf16(acc[mi][ni], alf, bhf[ni]);
            }
        }
    }
}

// ============================ fp16 single-A / pair-B GEMM core (3-stage, 2-MMA) ============================
template <int BM, int BN, int TMW, int TNW>
__device__ __forceinline__ void gemm_core_f16(
    const __half* __restrict__ Af, int lda,
    const __half* __restrict__ Bh, const __half* __restrict__ Bl, int ldb,
    int K, u32 sb, float (*acc)[4][4]) {
    constexpr int MI = BM / TMW / 16;
    constexpr int NI = BN / TNW / 8;
    static_assert(NI == 4, "epilogue layout assumes NI==4");
    constexpr u32 OFF_BH = BM * 64;
    constexpr u32 OFF_BL = BM * 64 + BN * 64;
    constexpr u32 SS = (BM + 2 * BN) * 64;
    const int tid = threadIdx.x;
    const int lane = tid & 31, wid = tid >> 5;
    const int wrow = (wid / TNW) * (BM / TMW);
    const int wcol = (wid % TNW) * (BN / TNW);
    const int NK = K >> 5;

    auto issue = [&](int kt) {
        const u32 st = sb + (u32)(kt % 3) * SS;
        const int k0 = kt << 5;
#pragma unroll
        for (int i = tid; i < BM * 4; i += 256) {
            int r = i >> 2, c = i & 3;
            u32 doff = (u32)(r * 64 + ((c ^ ((r >> 1) & 3)) << 4));
            cp16(st + doff, Af + (size_t)r * lda + k0 + c * 8);
        }
#pragma unroll
        for (int i = tid; i < BN * 4; i += 256) {
            int r = i >> 2, c = i & 3;
            u32 doff = (u32)(r * 64 + ((c ^ ((r >> 1) & 3)) << 4));
            cp16(st + OFF_BH + doff, Bh + (size_t)r * ldb + k0 + c * 8);
            cp16(st + OFF_BL + doff, Bl + (size_t)r * ldb + k0 + c * 8);
        }
        cp_commit();
    };

    issue(0);
    if (NK > 1) issue(1);
    for (int kt = 0; kt < NK; kt++) {
        if (kt + 1 < NK) cp_wait<1>();
        else             cp_wait<0>();
        __syncthreads();
        if (kt + 2 < NK) issue(kt + 2);
        const u32 st = sb + (u32)(kt % 3) * SS;
#pragma unroll
        for (int ks = 0; ks < 2; ks++) {
            u32 bhf[NI][2], blf[NI][2];
            {
                const int kc = ks * 2 + ((lane >> 3) & 1);
                const int rb = wcol + ((lane >> 4) << 3) + (lane & 7);
#pragma unroll
                for (int ni = 0; ni < NI; ni += 2) {
                    int r = rb + ni * 8;
                    u32 swz = (u32)(r * 64 + ((kc ^ ((r >> 1) & 3)) << 4));
                    ldm_x4(st + OFF_BH + swz, bhf[ni][0], bhf[ni][1], bhf[ni + 1][0], bhf[ni + 1][1]);
                    ldm_x4(st + OFF_BL + swz, blf[ni][0], blf[ni][1], blf[ni + 1][0], blf[ni + 1][1]);
                }
            }
            const int kcA = ks * 2 + (lane >> 4);
#pragma unroll
            for (int mi = 0; mi < MI; mi++) {
                int r = wrow + mi * 16 + (lane & 15);
                u32 a = st + (u32)(r * 64 + ((kcA ^ ((r >> 1) & 3)) << 4));
                u32 af[4];
                ldm_x4(a, af[0], af[1], af[2], af[3]);
#pragma unroll
                for (int ni = 0; ni < NI; ni++) mma_f16(acc[mi][ni], af, bhf[ni]);
#pragma unroll
                for (int ni = 0; ni < NI; ni++) mma_f16(acc[mi][ni], af, blf[ni]);
            }
        }
    }
}

#define GEMM_SMEM_BIG 98304   // qkv: 3 x 32768 (bf16 pair/pair, BM=BN=128)
#define SCORE_SMEM    81920   // score: A 32768 + 3 x 16384
#define AV_SMEM       49152   // av:   3 x 16384 (f16: A 8K + B 2x4K)
#define PROJ_SMEM     73728   // proj: 3 x 24576 (f16: A 8K + B 2x8K)

// ============================ fp32 -> bf16 hi/lo split ============================
__global__ __launch_bounds__(256) void split_kernel(const float* __restrict__ in,
                                                    __nv_bfloat16* __restrict__ hi,
                                                    __nv_bfloat16* __restrict__ lo, int n) {
    int i = (blockIdx.x * 256 + threadIdx.x) * 4;
    if (i >= n) return;
    float4 v = *reinterpret_cast<const float4*>(in + i);
    u32 l0, l1;
    u32 h0 = pack_hi_lo(v.x, v.y, l0);
    u32 h1 = pack_hi_lo(v.z, v.w, l1);
    *reinterpret_cast<uint2*>(hi + i) = make_uint2(h0, h1);
    *reinterpret_cast<uint2*>(lo + i) = make_uint2(l0, l1);
}

// ============================ fp32 -> fp16 hi/lo split ============================
__global__ __launch_bounds__(256) void split_f16_kernel(const float* __restrict__ in,
                                                        __half* __restrict__ hi,
                                                        __half* __restrict__ lo, int n) {
    int i = (blockIdx.x * 256 + threadIdx.x) * 4;
    if (i >= n) return;
    float4 v = *reinterpret_cast<const float4*>(in + i);
    float f[4] = {v.x, v.y, v.z, v.w};
    __half h[4], l[4];
#pragma unroll
    for (int j = 0; j < 4; j++) {
        h[j] = __float2half(f[j]);
        l[j] = __float2half(f[j] - __half2float(h[j]));
    }
    *reinterpret_cast<uint2*>(hi + i) = *reinterpret_cast<uint2*>(h);
    *reinterpret_cast<uint2*>(lo + i) = *reinterpret_cast<uint2*>(l);
}

// ============================ QKV GEMM + scatter (bf16 3-term, BN=128) ============================
__global__ __launch_bounds__(256, 2) void qkv_mma() {
    extern __shared__ char smem[];
    u32 sb = smem_u32(smem);
    const int n0 = blockIdx.x * 128, m0 = blockIdx.y * 128;
    float acc[4][4][4];
#pragma unroll
    for (int i = 0; i < 4; i++)
#pragma unroll
        for (int j = 0; j < 4; j++)
#pragma unroll
            for (int k = 0; k < 4; k++) acc[i][j][k] = 0.f;
    gemm_core<128, 128, 2, 4>(g_xh + (size_t)m0 * CC, g_xl + (size_t)m0 * CC, CC,
                              g_wqh + (size_t)n0 * CC, g_wql + (size_t)n0 * CC, CC,
                              CC, sb, acc);
    const int tid = threadIdx.x, lane = tid & 31, wid = tid >> 5;
    const int wm = wid >> 2, wn = wid & 3;
#pragma unroll
    for (int mi = 0; mi < 4; mi++)
#pragma unroll
        for (int ni = 0; ni < 4; ni++) {
            int c = n0 + wn * 32 + ni * 8 + (lane & 3) * 2;
            int t = c / CC, rc = c - t * CC, h = rc >> 6, d0 = rc & 63;
            float sc = (t == 0) ? SCALE : 1.f;
            __nv_bfloat16* ph = (t == 0) ? g_qh : (t == 1) ? g_kh : g_vh;
            __nv_bfloat16* pl = (t == 0) ? g_ql : (t == 1) ? g_kl : g_vl;
#pragma unroll
            for (int hf = 0; hf < 2; hf++) {
                int m = m0 + wm * 64 + mi * 16 + (lane >> 2) + hf * 8;
                int b = m / NN, ntok = m - b * NN;
                size_t base = ((size_t)(b * HH + h) * NN + ntok) * HDIM + d0;
                u32 lw, hw = pack_hi_lo(acc[mi][ni][hf * 2] * sc, acc[mi][ni][hf * 2 + 1] * sc, lw);
                *reinterpret_cast<u32*>(ph + base) = hw;
                *reinterpret_cast<u32*>(pl + base) = lw;
            }
        }
}

// ============================ transpose V -> vT[d][n] fp16 hi/lo ============================
__global__ __launch_bounds__(256) void transpose_v() {
    __shared__ float tf[32][33];
    int n0 = blockIdx.x * 32, d0 = blockIdx.y * 32, bh = blockIdx.z;
    int tx = threadIdx.x, ty = threadIdx.y;
#pragma unroll
    for (int i = 0; i < 4; i++) {
        int n = n0 + ty + i * 8;
        size_t s = ((size_t)bh * NN + n) * HDIM + d0 + tx;
        tf[ty + i * 8][tx] = __bfloat162float(g_vh[s]) + __bfloat162float(g_vl[s]);
    }
    __syncthreads();
#pragma unroll
    for (int i = 0; i < 4; i++) {
        int d = d0 + ty + i * 8;
        size_t t = ((size_t)bh * HDIM + d) * NN + n0 + tx;
        float f = tf[tx][ty + i * 8];
        __half h = __float2half(f);
        g_vthf[t] = h;
        g_vtlf[t] = __float2half(f - __half2float(h));
    }
}

// ============================ score: persistent-Q n-loop kernel (bf16 3-term) ============================
__global__ __launch_bounds__(256) void score_mma() {
    extern __shared__ char smem[];
    u32 sb = smem_u32(smem);
    const u32 A_HI = 0, A_LO = 16384, RING = 32768;
    const int m0 = blockIdx.x * 128, bhi = blockIdx.y;
    const int tid = threadIdx.x, lane = tid & 31, wid = tid >> 5;
    const int wm = wid >> 1, wn = wid & 1;
    const int wrow = wm * 32, wcol = wn * 32;

    const __nv_bfloat16* Qh = g_qh + ((size_t)bhi * NN + m0) * HDIM;
    const __nv_bfloat16* Ql = g_ql + ((size_t)bhi * NN + m0) * HDIM;
    const __nv_bfloat16* Kh = g_kh + (size_t)bhi * NN * HDIM;
    const __nv_bfloat16* Kl = g_kl + (size_t)bhi * NN * HDIM;

#pragma unroll
    for (int i = tid; i < 128 * 8; i += 256) {
        int r = i >> 3, cc = i & 7, kt = cc >> 2, c = cc & 3;
        u32 doff = (u32)(kt * 8192 + r * 64 + ((c ^ ((r >> 1) & 3)) << 4));
        size_t so = (size_t)r * HDIM + kt * 32 + c * 8;
        cp16(sb + A_HI + doff, Qh + so);
        cp16(sb + A_LO + doff, Ql + so);
    }
    cp_commit();

    auto issueB = [&](int nt) {
        const u32 st = sb + RING + (u32)(nt % 3) * 16384;
#pragma unroll
        for (int i = tid; i < 64 * 8; i += 256) {
            int r = i >> 3, cc = i & 7, kt = cc >> 2, c = cc & 3;
            u32 doff = (u32)(kt * 4096 + r * 64 + ((c ^ ((r >> 1) & 3)) << 4));
            size_t so = (size_t)(nt * 64 + r) * HDIM + kt * 32 + c * 8;
            cp16(st + doff, Kh + so);
            cp16(st + 8192 + doff, Kl + so);
        }
        cp_commit();
    };
    issueB(0); issueB(1);

    float* outb = g_attn + (size_t)bhi * NN * NN;
    for (int nt = 0; nt < 9; nt++) {
        if (nt < 8) cp_wait<1>();
        else        cp_wait<0>();
        __syncthreads();
        if (nt + 2 < 9) issueB(nt + 2);
        const u32 st = sb + RING + (u32)(nt % 3) * 16384;

        float acc[2][4][4];
#pragma unroll
        for (int i = 0; i < 2; i++)
#pragma unroll
            for (int j = 0; j < 4; j++)
#pragma unroll
                for (int k = 0; k < 4; k++) acc[i][j][k] = 0.f;

#pragma unroll
        for (int kt = 0; kt < 2; kt++)
#pragma unroll
            for (int ks = 0; ks < 2; ks++) {
                u32 bhf[4][2], blf[4][2];
                {
                    const int kc = ks * 2 + ((lane >> 3) & 1);
                    const int rb = wcol + ((lane >> 4) << 3) + (lane & 7);
#pragma unroll
                    for (int ni = 0; ni < 4; ni += 2) {
                        int r = rb + ni * 8;
                        u32 swz = (u32)(kt * 4096 + r * 64 + ((kc ^ ((r >> 1) & 3)) << 4));
                        ldm_x4(st + swz, bhf[ni][0], bhf[ni][1], bhf[ni + 1][0], bhf[ni + 1][1]);
                        ldm_x4(st + 8192 + swz, blf[ni][0], blf[ni][1], blf[ni + 1][0], blf[ni + 1][1]);
                    }
                }
                const int kcA = ks * 2 + (lane >> 4);
#pragma unroll
                for (int mi = 0; mi < 2; mi++) {
                    int r = wrow + mi * 16 + (lane & 15);
                    u32 aoff = (u32)(kt * 8192 + r * 64 + ((kcA ^ ((r >> 1) & 3)) << 4));
                    u32 ahf[4], alf[4];
                    ldm_x4(sb + A_HI + aoff, ahf[0], ahf[1], ahf[2], ahf[3]);
                    ldm_x4(sb + A_LO + aoff, alf[0], alf[1], alf[2], alf[3]);
#pragma unroll
                    for (int ni = 0; ni < 4; ni++) mma_bf16(acc[mi][ni], ahf, bhf[ni]);
#pragma unroll
                    for (int ni = 0; ni < 4; ni++) mma_bf16(acc[mi][ni], ahf, blf[ni]);
#pragma unroll
                    for (int ni = 0; ni < 4; ni++) mma_bf16(acc[mi][ni], alf, bhf[ni]);
                }
            }

        const int n0 = nt * 64;
#pragma unroll
        for (int mi = 0; mi < 2; mi++)
#pragma unroll
            for (int ni = 0; ni < 4; ni++) {
                int c = n0 + wn * 32 + ni * 8 + (lane & 3) * 2;
#pragma unroll
                for (int hf = 0; hf < 2; hf++) {
                    int m = m0 + wm * 32 + mi * 16 + (lane >> 2) + hf * 8;
                    if (m < NN)
                        *reinterpret_cast<float2*>(outb + (size_t)m * NN + c) =
                            make_float2(acc[mi][ni][hf * 2], acc[mi][ni][hf * 2 + 1]);
                }
            }
    }
}

// ============================ softmax + both mixes; attn2 out = single fp16 ============================
__global__ __launch_bounds__(384) void softmax_mix_kernel(const float* __restrict__ Wl,
                                                          const float* __restrict__ bl,
                                                          const float* __restrict__ Ww,
                                                          const float* __restrict__ bw) {
    __shared__ __align__(16) float sm[HH][NN];
    __shared__ float wls[HH * HH], bls[HH], wws[HH * HH], bws[HH];
    const int bm = blockIdx.x;
    const int b = bm / NN, m = bm % NN;
    const int tid = threadIdx.x, lane = tid & 31, wid = tid >> 5;

    if (tid < HH * HH) { wls[tid] = Wl[tid]; wws[tid] = Ww[tid]; }
    if (tid < HH) { bls[tid] = bl[tid]; bws[tid] = bw[tid]; }

    for (int idx = tid; idx < HH * NN / 4; idx += 384) {
        int h = idx / (NN / 4), n4 = idx - h * (NN / 4);
        float4 v = *reinterpret_cast<const float4*>(
            &g_attn[((size_t)(b * HH + h) * NN + m) * NN + n4 * 4]);
        *reinterpret_cast<float4*>(&sm[h][n4 * 4]) = v;
    }
    __syncthreads();

    for (int n = tid; n < NN; n += 384) {
        float p[HH];
#pragma unroll
        for (int h = 0; h < HH; h++) p[h] = sm[h][n];
#pragma unroll
        for (int g = 0; g < HH; g++) {
            float o = bls[g];
#pragma unroll
            for (int h = 0; h < HH; h++) o += wls[g * HH + h] * p[h];
            sm[g][n] = o;
        }
    }
    __syncthreads();

    {
        const int h = wid;
        float mx = -1e30f;
        for (int n = lane; n < NN; n += 32) mx = fmaxf(mx, sm[h][n]);
#pragma unroll
        for (int o = 16; o > 0; o >>= 1) mx = fmaxf(mx, __shfl_xor_sync(0xffffffffu, mx, o));
        float sum = 0.f;
        for (int n = lane; n < NN; n += 32) {
            float e = __expf(sm[h][n] - mx);
            sm[h][n] = e; sum += e;
        }
#pragma unroll
        for (int o = 16; o > 0; o >>= 1) sum += __shfl_xor_sync(0xffffffffu, sum, o);
        float inv = 1.f / sum;
        for (int n = lane; n < NN; n += 32) sm[h][n] *= inv;
    }
    __syncthreads();

    for (int n2 = tid; n2 < NN / 2; n2 += 384) {
        int n = n2 * 2;
        float p0[HH], p1[HH];
#pragma unroll
        for (int h = 0; h < HH; h++) { p0[h] = sm[h][n]; p1[h] = sm[h][n + 1]; }
#pragma unroll
        for (int g = 0; g < HH; g++) {
            float o0 = bws[g], o1 = bws[g];
#pragma unroll
            for (int h = 0; h < HH; h++) { o0 += wws[g * HH + h] * p0[h]; o1 += wws[g * HH + h] * p1[h]; }
            size_t idx = ((size_t)(b * HH + g) * NN + m) * NN + n;
            *reinterpret_cast<__half2*>(g_a2f + idx) = __floats2half2_rn(o0, o1);
        }
    }
}

// ============================ O = attn2 @ V per (b,h)  (fp16 2-MMA) ============================
// grid (5, 192). K = 576.
__global__ __launch_bounds__(256, 3) void av_mma() {
    extern __shared__ char smem[];
    u32 sb = smem_u32(smem);
    const int m0 = blockIdx.x * 128, bh = blockIdx.y;
    float acc[2][4][4];
#pragma unroll
    for (int i = 0; i < 2; i++)
#pragma unroll
        for (int j = 0; j < 4; j++)
#pragma unroll
            for (int k = 0; k < 4; k++) acc[i][j][k] = 0.f;
    const size_t ab = (size_t)bh * NN * NN + (size_t)m0 * NN;
    const size_t bb = (size_t)bh * HDIM * NN;
    gemm_core_f16<128, 64, 4, 2>(g_a2f + ab, NN,
                                 g_vthf + bb, g_vtlf + bb, NN, NN, sb, acc);
    const int tid = threadIdx.x, lane = tid & 31, wid = tid >> 5;
    const int wm = wid >> 1, wn = wid & 1;
    const int b = bh / HH, h = bh - b * HH;
#pragma unroll
    for (int mi = 0; mi < 2; mi++)
#pragma unroll
        for (int ni = 0; ni < 4; ni++) {
            int dc = wn * 32 + ni * 8 + (lane & 3) * 2;
#pragma unroll
            for (int hf = 0; hf < 2; hf++) {
                int m = m0 + wm * 32 + mi * 16 + (lane >> 2) + hf * 8;
                if (m < NN) {
                    size_t base = ((size_t)b * NN + m) * CC + h * HDIM + dc;
                    *reinterpret_cast<__half2*>(g_o1f + base) =
                        __floats2half2_rn(acc[mi][ni][hf * 2], acc[mi][ni][hf * 2 + 1]);
                }
            }
        }
}

// ============================ out = o1 @ Wproj^T + bias (fp16 2-MMA, BN=128) ============================
// grid (6, 72)
__global__ __launch_bounds__(256, 2) void proj_mma(const float* __restrict__ bias,
                                                   float* __restrict__ out) {
    extern __shared__ char smem[];
    u32 sb = smem_u32(smem);
    const int n0 = blockIdx.x * 128, m0 = blockIdx.y * 128;
    float acc[4][4][4];
#pragma unroll
    for (int i = 0; i < 4; i++)
#pragma unroll
        for (int j = 0; j < 4; j++)
#pragma unroll
            for (int k = 0; k < 4; k++) acc[i][j][k] = 0.f;
    gemm_core_f16<128, 128, 2, 4>(g_o1f + (size_t)m0 * CC, CC,
                                  g_wphf + (size_t)n0 * CC, g_wplf + (size_t)n0 * CC, CC,
                                  CC, sb, acc);
    const int tid = threadIdx.x, lane = tid & 31, wid = tid >> 5;
    const int wm = wid >> 2, wn = wid & 3;
#pragma unroll
    for (int mi = 0; mi < 4; mi++)
#pragma unroll
        for (int ni = 0; ni < 4; ni++) {
            int c = n0 + wn * 32 + ni * 8 + (lane & 3) * 2;
            float b0 = __ldg(&bias[c]), b1 = __ldg(&bias[c + 1]);
#pragma unroll
            for (int hf = 0; hf < 2; hf++) {
                int m = m0 + wm * 64 + mi * 16 + (lane >> 2) + hf * 8;
                *reinterpret_cast<float2*>(out + (size_t)m * CC + c) =
                    make_float2(acc[mi][ni][hf * 2] + b0, acc[mi][ni][hf * 2 + 1] + b1);
            }
        }
}

// ============================ launch ============================
extern "C" void kernel_launch(void* const* d_in, const int* in_sizes, int n_in,
                              void* d_out, int out_size) {
    const float* x     = (const float*)d_in[0];
    const float* Wqkv  = (const float*)d_in[1];
    const float* Wl    = (const float*)d_in[2];
    const float* bl    = (const float*)d_in[3];
    const float* Ww    = (const float*)d_in[4];
    const float* bw    = (const float*)d_in[5];
    const float* Wproj = (const float*)d_in[6];
    const float* bproj = (const float*)d_in[7];
    float* out = (float*)d_out;

    static bool attr_done = false;
    if (!attr_done) {
        cudaFuncSetAttribute(qkv_mma,   cudaFuncAttributeMaxDynamicSharedMemorySize, GEMM_SMEM_BIG);
        cudaFuncSetAttribute(score_mma, cudaFuncAttributeMaxDynamicSharedMemorySize, SCORE_SMEM);
        cudaFuncSetAttribute(av_mma,    cudaFuncAttributeMaxDynamicSharedMemorySize, AV_SMEM);
        cudaFuncSetAttribute(proj_mma,  cudaFuncAttributeMaxDynamicSharedMemorySize, PROJ_SMEM);
        attr_done = true;
    }

    __nv_bfloat16 *xh, *xl, *wqh, *wql;
    __half *wphf, *wplf;
    cudaGetSymbolAddress((void**)&xh, g_xh);     cudaGetSymbolAddress((void**)&xl, g_xl);
    cudaGetSymbolAddress((void**)&wqh, g_wqh);   cudaGetSymbolAddress((void**)&wql, g_wql);
    cudaGetSymbolAddress((void**)&wphf, g_wphf); cudaGetSymbolAddress((void**)&wplf, g_wplf);

    split_kernel<<<(MTOT * CC / 4 + 255) / 256, 256>>>(x, xh, xl, MTOT * CC);
    split_kernel<<<(3 * CC * CC / 4 + 255) / 256, 256>>>(Wqkv, wqh, wql, 3 * CC * CC);
    split_f16_kernel<<<(CC * CC / 4 + 255) / 256, 256>>>(Wproj, wphf, wplf, CC * CC);

    qkv_mma<<<dim3(18, 72), 256, GEMM_SMEM_BIG>>>();
    transpose_v<<<dim3(18, 2, BB * HH), dim3(32, 8)>>>();
    score_mma<<<dim3(5, BB * HH), 256, SCORE_SMEM>>>();
    softmax_mix_kernel<<<MTOT, 384>>>(Wl, bl, Ww, bw);
    av_mma<<<dim3(5, BB * HH), 256, AV_SMEM>>>();
    proj_mma<<<dim3(6, 72), 256, PROJ_SMEM>>>(bproj, out);
}

// round 12
// speedup vs baseline: 1.2067x; 1.1062x over previous
#include <cuda_runtime.h>
#include <cuda_bf16.h>
#include <cuda_fp16.h>

// Talking-heads attention via mma.sync tensor cores (plain sm_100 ISA).
// v11b: identical strategy to v11 (infra-failed, audit-clean); pads widened.
//   qkv : A = x single fp16, B = Wqkv fp16 hi/lo  -> 2 MMAs/k-step
//   score: q,k bf16 hi/lo, 3 MMAs (feeds softmax; kept clean)
//   av  : attn2 single fp16 x V^T single fp16     -> 1 MMA/k-step
//   proj: o1 single fp16 x Wproj fp16 hi/lo       -> 2 MMAs/k-step

#define BB 16
#define NN 576
#define CC 768
#define HH 12
#define HDIM 64
#define MTOT (BB * NN)
#define SCALE 0.125f
#define ATT ((size_t)BB * HH * NN * NN)
#define QKE (BB * HH * NN * HDIM)

typedef unsigned int u32;

// ============================ PTX helpers ============================
__device__ __forceinline__ u32 smem_u32(const void* p) {
    u32 a;
    asm("{ .reg .u64 t; cvta.to.shared.u64 t, %1; cvt.u32.u64 %0, t; }" : "=r"(a) : "l"(p));
    return a;
}
__device__ __forceinline__ void cp16(u32 dst, const void* src) {
    asm volatile("cp.async.cg.shared.global [%0], [%1], 16;" :: "r"(dst), "l"(src));
}
__device__ __forceinline__ void cp_commit() {
    asm volatile("cp.async.commit_group;" ::: "memory");
}
template <int N>
__device__ __forceinline__ void cp_wait() {
    asm volatile("cp.async.wait_group %0;" :: "n"(N) : "memory");
}
__device__ __forceinline__ void ldm_x4(u32 a, u32& r0, u32& r1, u32& r2, u32& r3) {
    asm volatile("ldmatrix.sync.aligned.m8n8.x4.shared.b16 {%0,%1,%2,%3}, [%4];"
                 : "=r"(r0), "=r"(r1), "=r"(r2), "=r"(r3) : "r"(a));
}
__device__ __forceinline__ void mma_bf16(float* d, const u32* a, const u32* b) {
    asm volatile("mma.sync.aligned.m16n8k16.row.col.f32.bf16.bf16.f32 "
                 "{%0,%1,%2,%3}, {%4,%5,%6,%7}, {%8,%9}, {%0,%1,%2,%3};"
                 : "+f"(d[0]), "+f"(d[1]), "+f"(d[2]), "+f"(d[3])
                 : "r"(a[0]), "r"(a[1]), "r"(a[2]), "r"(a[3]), "r"(b[0]), "r"(b[1]));
}
__device__ __forceinline__ void mma_f16(float* d, const u32* a, const u32* b) {
    asm volatile("mma.sync.aligned.m16n8k16.row.col.f32.f16.f16.f32 "
                 "{%0,%1,%2,%3}, {%4,%5,%6,%7}, {%8,%9}, {%0,%1,%2,%3};"
                 : "+f"(d[0]), "+f"(d[1]), "+f"(d[2]), "+f"(d[3])
                 : "r"(a[0]), "r"(a[1]), "r"(a[2]), "r"(a[3]), "r"(b[0]), "r"(b[1]));
}

// ============================ scratch (16B-aligned; generous pads) ============================
__device__ __align__(16) __half g_xf[MTOT * CC];                          // x single fp16
__device__ __align__(16) __half g_wqhf[3 * CC * CC], g_wqlf[3 * CC * CC]; // Wqkv fp16 hi/lo
__device__ __align__(16) __nv_bfloat16 g_qh[QKE + 128 * HDIM], g_ql[QKE + 128 * HDIM];
__device__ __align__(16) __nv_bfloat16 g_kh[QKE + 128 * HDIM], g_kl[QKE + 128 * HDIM];
__device__ __align__(16) __half g_vf[QKE];                                // v single fp16
__device__ __align__(16) __half g_vtf[QKE];                               // v^T single fp16
__device__ __align__(16) float g_attn[ATT];
__device__ __align__(16) __half g_a2f[ATT + 128 * NN];                    // attn2 single fp16
__device__ __align__(16) __half g_o1f[MTOT * CC];                         // o1 single fp16
__device__ __align__(16) __half g_wphf[CC * CC], g_wplf[CC * CC];         // Wproj fp16 hi/lo

__device__ __forceinline__ u32 pack_hi_lo(float f0, float f1, u32& lo_out) {
    __nv_bfloat16 h0 = __float2bfloat16(f0);
    __nv_bfloat16 h1 = __float2bfloat16(f1);
    __nv_bfloat16 l0 = __float2bfloat16(f0 - __bfloat162float(h0));
    __nv_bfloat16 l1 = __float2bfloat16(f1 - __bfloat162float(h1));
    u32 hw = ((u32)__bfloat16_as_ushort(h1) << 16) | __bfloat16_as_ushort(h0);
    lo_out = ((u32)__bfloat16_as_ushort(l1) << 16) | __bfloat16_as_ushort(l0);
    return hw;
}

// ============================ fp16 single-A / pair-B GEMM core (3-stage, 2-MMA) ============================
template <int BM, int BN, int TMW, int TNW>
__device__ __forceinline__ void gemm_core_f16(
    const __half* __restrict__ Af, int lda,
    const __half* __restrict__ Bh, const __half* __restrict__ Bl, int ldb,
    int K, u32 sb, float (*acc)[4][4]) {
    constexpr int MI = BM / TMW / 16;
    constexpr int NI = BN / TNW / 8;
    static_assert(NI == 4, "epilogue layout assumes NI==4");
    constexpr u32 OFF_BH = BM * 64;
    constexpr u32 OFF_BL = BM * 64 + BN * 64;
    constexpr u32 SS = (BM + 2 * BN) * 64;
    const int tid = threadIdx.x;
    const int lane = tid & 31, wid = tid >> 5;
    const int wrow = (wid / TNW) * (BM / TMW);
    const int wcol = (wid % TNW) * (BN / TNW);
    const int NK = K >> 5;

    auto issue = [&](int kt) {
        const u32 st = sb + (u32)(kt % 3) * SS;
        const int k0 = kt << 5;
#pragma unroll
        for (int i = tid; i < BM * 4; i += 256) {
            int r = i >> 2, c = i & 3;
            u32 doff = (u32)(r * 64 + ((c ^ ((r >> 1) & 3)) << 4));
            cp16(st + doff, Af + (size_t)r * lda + k0 + c * 8);
        }
#pragma unroll
        for (int i = tid; i < BN * 4; i += 256) {
            int r = i >> 2, c = i & 3;
            u32 doff = (u32)(r * 64 + ((c ^ ((r >> 1) & 3)) << 4));
            cp16(st + OFF_BH + doff, Bh + (size_t)r * ldb + k0 + c * 8);
            cp16(st + OFF_BL + doff, Bl + (size_t)r * ldb + k0 + c * 8);
        }
        cp_commit();
    };

    issue(0);
    if (NK > 1) issue(1);
    for (int kt = 0; kt < NK; kt++) {
        if (kt + 1 < NK) cp_wait<1>();
        else             cp_wait<0>();
        __syncthreads();
        if (kt + 2 < NK) issue(kt + 2);
        const u32 st = sb + (u32)(kt % 3) * SS;
#pragma unroll
        for (int ks = 0; ks < 2; ks++) {
            u32 bhf[NI][2], blf[NI][2];
            {
                const int kc = ks * 2 + ((lane >> 3) & 1);
                const int rb = wcol + ((lane >> 4) << 3) + (lane & 7);
#pragma unroll
                for (int ni = 0; ni < NI; ni += 2) {
                    int r = rb + ni * 8;
                    u32 swz = (u32)(r * 64 + ((kc ^ ((r >> 1) & 3)) << 4));
                    ldm_x4(st + OFF_BH + swz, bhf[ni][0], bhf[ni][1], bhf[ni + 1][0], bhf[ni + 1][1]);
                    ldm_x4(st + OFF_BL + swz, blf[ni][0], blf[ni][1], blf[ni + 1][0], blf[ni + 1][1]);
                }
            }
            const int kcA = ks * 2 + (lane >> 4);
#pragma unroll
            for (int mi = 0; mi < MI; mi++) {
                int r = wrow + mi * 16 + (lane & 15);
                u32 a = st + (u32)(r * 64 + ((kcA ^ ((r >> 1) & 3)) << 4));
                u32 af[4];
                ldm_x4(a, af[0], af[1], af[2], af[3]);
#pragma unroll
                for (int ni = 0; ni < NI; ni++) mma_f16(acc[mi][ni], af, bhf[ni]);
#pragma unroll
                for (int ni = 0; ni < NI; ni++) mma_f16(acc[mi][ni], af, blf[ni]);
            }
        }
    }
}

// ============================ fp16 single/single GEMM core (3-stage, 1-MMA) ============================
template <int BM, int BN, int TMW, int TNW>
__device__ __forceinline__ void gemm_core_f16s(
    const __half* __restrict__ Af, int lda,
    const __half* __restrict__ Bf, int ldb,
    int K, u32 sb, float (*acc)[4][4]) {
    constexpr int MI = BM / TMW / 16;
    constexpr int NI = BN / TNW / 8;
    static_assert(NI == 4, "epilogue layout assumes NI==4");
    constexpr u32 OFF_B = BM * 64;
    constexpr u32 SS = (BM + BN) * 64;
    const int tid = threadIdx.x;
    const int lane = tid & 31, wid = tid >> 5;
    const int wrow = (wid / TNW) * (BM / TMW);
    const int wcol = (wid % TNW) * (BN / TNW);
    const int NK = K >> 5;

    auto issue = [&](int kt) {
        const u32 st = sb + (u32)(kt % 3) * SS;
        const int k0 = kt << 5;
#pragma unroll
        for (int i = tid; i < BM * 4; i += 256) {
            int r = i >> 2, c = i & 3;
            u32 doff = (u32)(r * 64 + ((c ^ ((r >> 1) & 3)) << 4));
            cp16(st + doff, Af + (size_t)r * lda + k0 + c * 8);
        }
#pragma unroll
        for (int i = tid; i < BN * 4; i += 256) {
            int r = i >> 2, c = i & 3;
            u32 doff = (u32)(r * 64 + ((c ^ ((r >> 1) & 3)) << 4));
            cp16(st + OFF_B + doff, Bf + (size_t)r * ldb + k0 + c * 8);
        }
        cp_commit();
    };

    issue(0);
    if (NK > 1) issue(1);
    for (int kt = 0; kt < NK; kt++) {
        if (kt + 1 < NK) cp_wait<1>();
        else             cp_wait<0>();
        __syncthreads();
        if (kt + 2 < NK) issue(kt + 2);
        const u32 st = sb + (u32)(kt % 3) * SS;
#pragma unroll
        for (int ks = 0; ks < 2; ks++) {
            u32 bf[NI][2];
            {
                const int kc = ks * 2 + ((lane >> 3) & 1);
                const int rb = wcol + ((lane >> 4) << 3) + (lane & 7);
#pragma unroll
                for (int ni = 0; ni < NI; ni += 2) {
                    int r = rb + ni * 8;
                    u32 swz = (u32)(r * 64 + ((kc ^ ((r >> 1) & 3)) << 4));
                    ldm_x4(st + OFF_B + swz, bf[ni][0], bf[ni][1], bf[ni + 1][0], bf[ni + 1][1]);
                }
            }
            const int kcA = ks * 2 + (lane >> 4);
#pragma unroll
            for (int mi = 0; mi < MI; mi++) {
                int r = wrow + mi * 16 + (lane & 15);
                u32 a = st + (u32)(r * 64 + ((kcA ^ ((r >> 1) & 3)) << 4));
                u32 af[4];
                ldm_x4(a, af[0], af[1], af[2], af[3]);
#pragma unroll
                for (int ni = 0; ni < NI; ni++) mma_f16(acc[mi][ni], af, bf[ni]);
            }
        }
    }
}

#define QKV_SMEM   73728   // 3 x 24576 (f16: A 8K + B 2x8K)
#define SCORE_SMEM 81920   // A 32768 + 3 x 16384 (bf16 pair/pair)
#define AV_SMEM    36864   // 3 x 12288 (f16s: A 8K + B 4K)
#define PROJ_SMEM  73728   // 3 x 24576

// ============================ fp32 -> fp16 single ============================
__global__ __launch_bounds__(256) void split_f16s_kernel(const float* __restrict__ in,
                                                         __half* __restrict__ o, int n) {
    int i = (blockIdx.x * 256 + threadIdx.x) * 4;
    if (i >= n) return;
    float4 v = *reinterpret_cast<const float4*>(in + i);
    __half2 a = __floats2half2_rn(v.x, v.y);
    __half2 b = __floats2half2_rn(v.z, v.w);
    *reinterpret_cast<uint2*>(o + i) = make_uint2(*(u32*)&a, *(u32*)&b);
}

// ============================ fp32 -> fp16 hi/lo split ============================
__global__ __launch_bounds__(256) void split_f16_kernel(const float* __restrict__ in,
                                                        __half* __restrict__ hi,
                                                        __half* __restrict__ lo, int n) {
    int i = (blockIdx.x * 256 + threadIdx.x) * 4;
    if (i >= n) return;
    float4 v = *reinterpret_cast<const float4*>(in + i);
    float f[4] = {v.x, v.y, v.z, v.w};
    __half h[4], l[4];
#pragma unroll
    for (int j = 0; j < 4; j++) {
        h[j] = __float2half(f[j]);
        l[j] = __float2half(f[j] - __half2float(h[j]));
    }
    *reinterpret_cast<uint2*>(hi + i) = *reinterpret_cast<uint2*>(h);
    *reinterpret_cast<uint2*>(lo + i) = *reinterpret_cast<uint2*>(l);
}

// ============================ QKV GEMM + scatter (f16 2-MMA, BN=128) ============================
// grid (18, 72)
__global__ __launch_bounds__(256, 2) void qkv_mma() {
    extern __shared__ char smem[];
    u32 sb = smem_u32(smem);
    const int n0 = blockIdx.x * 128, m0 = blockIdx.y * 128;
    float acc[4][4][4];
#pragma unroll
    for (int i = 0; i < 4; i++)
#pragma unroll
        for (int j = 0; j < 4; j++)
#pragma unroll
            for (int k = 0; k < 4; k++) acc[i][j][k] = 0.f;
    gemm_core_f16<128, 128, 2, 4>(g_xf + (size_t)m0 * CC, CC,
                                  g_wqhf + (size_t)n0 * CC, g_wqlf + (size_t)n0 * CC, CC,
                                  CC, sb, acc);
    const int tid = threadIdx.x, lane = tid & 31, wid = tid >> 5;
    const int wm = wid >> 2, wn = wid & 3;
#pragma unroll
    for (int mi = 0; mi < 4; mi++)
#pragma unroll
        for (int ni = 0; ni < 4; ni++) {
            int c = n0 + wn * 32 + ni * 8 + (lane & 3) * 2;
            int t = c / CC, rc = c - t * CC, h = rc >> 6, d0 = rc & 63;
#pragma unroll
            for (int hf = 0; hf < 2; hf++) {
                int m = m0 + wm * 64 + mi * 16 + (lane >> 2) + hf * 8;
                int b = m / NN, ntok = m - b * NN;
                size_t base = ((size_t)(b * HH + h) * NN + ntok) * HDIM + d0;
                float f0 = acc[mi][ni][hf * 2], f1 = acc[mi][ni][hf * 2 + 1];
                if (t == 2) {
                    *reinterpret_cast<__half2*>(g_vf + base) = __floats2half2_rn(f0, f1);
                } else {
                    if (t == 0) { f0 *= SCALE; f1 *= SCALE; }
                    __nv_bfloat16* ph = (t == 0) ? g_qh : g_kh;
                    __nv_bfloat16* pl = (t == 0) ? g_ql : g_kl;
                    u32 lw, hw = pack_hi_lo(f0, f1, lw);
                    *reinterpret_cast<u32*>(ph + base) = hw;
                    *reinterpret_cast<u32*>(pl + base) = lw;
                }
            }
        }
}

// ============================ transpose V -> vT[d][n] (single fp16) ============================
__global__ __launch_bounds__(256) void transpose_v() {
    __shared__ __half tf[32][34];
    int n0 = blockIdx.x * 32, d0 = blockIdx.y * 32, bh = blockIdx.z;
    int tx = threadIdx.x, ty = threadIdx.y;
#pragma unroll
    for (int i = 0; i < 4; i++) {
        int n = n0 + ty + i * 8;
        tf[ty + i * 8][tx] = g_vf[((size_t)bh * NN + n) * HDIM + d0 + tx];
    }
    __syncthreads();
#pragma unroll
    for (int i = 0; i < 4; i++) {
        int d = d0 + ty + i * 8;
        g_vtf[((size_t)bh * HDIM + d) * NN + n0 + tx] = tf[tx][ty + i * 8];
    }
}

// ============================ score: persistent-Q n-loop kernel (bf16 3-term) ============================
__global__ __launch_bounds__(256) void score_mma() {
    extern __shared__ char smem[];
    u32 sb = smem_u32(smem);
    const u32 A_HI = 0, A_LO = 16384, RING = 32768;
    const int m0 = blockIdx.x * 128, bhi = blockIdx.y;
    const int tid = threadIdx.x, lane = tid & 31, wid = tid >> 5;
    const int wm = wid >> 1, wn = wid & 1;
    const int wrow = wm * 32, wcol = wn * 32;

    const __nv_bfloat16* Qh = g_qh + ((size_t)bhi * NN + m0) * HDIM;
    const __nv_bfloat16* Ql = g_ql + ((size_t)bhi * NN + m0) * HDIM;
    const __nv_bfloat16* Kh = g_kh + (size_t)bhi * NN * HDIM;
    const __nv_bfloat16* Kl = g_kl + (size_t)bhi * NN * HDIM;

#pragma unroll
    for (int i = tid; i < 128 * 8; i += 256) {
        int r = i >> 3, cc = i & 7, kt = cc >> 2, c = cc & 3;
        u32 doff = (u32)(kt * 8192 + r * 64 + ((c ^ ((r >> 1) & 3)) << 4));
        size_t so = (size_t)r * HDIM + kt * 32 + c * 8;
        cp16(sb + A_HI + doff, Qh + so);
        cp16(sb + A_LO + doff, Ql + so);
    }
    cp_commit();

    auto issueB = [&](int nt) {
        const u32 st = sb + RING + (u32)(nt % 3) * 16384;
#pragma unroll
        for (int i = tid; i < 64 * 8; i += 256) {
            int r = i >> 3, cc = i & 7, kt = cc >> 2, c = cc & 3;
            u32 doff = (u32)(kt * 4096 + r * 64 + ((c ^ ((r >> 1) & 3)) << 4));
            size_t so = (size_t)(nt * 64 + r) * HDIM + kt * 32 + c * 8;
            cp16(st + doff, Kh + so);
            cp16(st + 8192 + doff, Kl + so);
        }
        cp_commit();
    };
    issueB(0); issueB(1);

    float* outb = g_attn + (size_t)bhi * NN * NN;
    for (int nt = 0; nt < 9; nt++) {
        if (nt < 8) cp_wait<1>();
        else        cp_wait<0>();
        __syncthreads();
        if (nt + 2 < 9) issueB(nt + 2);
        const u32 st = sb + RING + (u32)(nt % 3) * 16384;

        float acc[2][4][4];
#pragma unroll
        for (int i = 0; i < 2; i++)
#pragma unroll
            for (int j = 0; j < 4; j++)
#pragma unroll
                for (int k = 0; k < 4; k++) acc[i][j][k] = 0.f;

#pragma unroll
        for (int kt = 0; kt < 2; kt++)
#pragma unroll
            for (int ks = 0; ks < 2; ks++) {
                u32 bhf[4][2], blf[4][2];
                {
                    const int kc = ks * 2 + ((lane >> 3) & 1);
                    const int rb = wcol + ((lane >> 4) << 3) + (lane & 7);
#pragma unroll
                    for (int ni = 0; ni < 4; ni += 2) {
                        int r = rb + ni * 8;
                        u32 swz = (u32)(kt * 4096 + r * 64 + ((kc ^ ((r >> 1) & 3)) << 4));
                        ldm_x4(st + swz, bhf[ni][0], bhf[ni][1], bhf[ni + 1][0], bhf[ni + 1][1]);
                        ldm_x4(st + 8192 + swz, blf[ni][0], blf[ni][1], blf[ni + 1][0], blf[ni + 1][1]);
                    }
                }
                const int kcA = ks * 2 + (lane >> 4);
#pragma unroll
                for (int mi = 0; mi < 2; mi++) {
                    int r = wrow + mi * 16 + (lane & 15);
                    u32 aoff = (u32)(kt * 8192 + r * 64 + ((kcA ^ ((r >> 1) & 3)) << 4));
                    u32 ahf[4], alf[4];
                    ldm_x4(sb + A_HI + aoff, ahf[0], ahf[1], ahf[2], ahf[3]);
                    ldm_x4(sb + A_LO + aoff, alf[0], alf[1], alf[2], alf[3]);
#pragma unroll
                    for (int ni = 0; ni < 4; ni++) mma_bf16(acc[mi][ni], ahf, bhf[ni]);
#pragma unroll
                    for (int ni = 0; ni < 4; ni++) mma_bf16(acc[mi][ni], ahf, blf[ni]);
#pragma unroll
                    for (int ni = 0; ni < 4; ni++) mma_bf16(acc[mi][ni], alf, bhf[ni]);
                }
            }

        const int n0 = nt * 64;
#pragma unroll
        for (int mi = 0; mi < 2; mi++)
#pragma unroll
            for (int ni = 0; ni < 4; ni++) {
                int c = n0 + wn * 32 + ni * 8 + (lane & 3) * 2;
#pragma unroll
                for (int hf = 0; hf < 2; hf++) {
                    int m = m0 + wm * 32 + mi * 16 + (lane >> 2) + hf * 8;
                    if (m < NN)
                        *reinterpret_cast<float2*>(outb + (size_t)m * NN + c) =
                            make_float2(acc[mi][ni][hf * 2], acc[mi][ni][hf * 2 + 1]);
                }
            }
    }
}

// ============================ softmax + both mixes; attn2 out = single fp16 ============================
__global__ __launch_bounds__(384) void softmax_mix_kernel(const float* __restrict__ Wl,
                                                          const float* __restrict__ bl,
                                                          const float* __restrict__ Ww,
                                                          const float* __restrict__ bw) {
    __shared__ __align__(16) float sm[HH][NN];
    __shared__ float wls[HH * HH], bls[HH], wws[HH * HH], bws[HH];
    const int bm = blockIdx.x;
    const int b = bm / NN, m = bm % NN;
    const int tid = threadIdx.x, lane = tid & 31, wid = tid >> 5;

    if (tid < HH * HH) { wls[tid] = Wl[tid]; wws[tid] = Ww[tid]; }
    if (tid < HH) { bls[tid] = bl[tid]; bws[tid] = bw[tid]; }

    for (int idx = tid; idx < HH * NN / 4; idx += 384) {
        int h = idx / (NN / 4), n4 = idx - h * (NN / 4);
        float4 v = *reinterpret_cast<const float4*>(
            &g_attn[((size_t)(b * HH + h) * NN + m) * NN + n4 * 4]);
        *reinterpret_cast<float4*>(&sm[h][n4 * 4]) = v;
    }
    __syncthreads();

    for (int n = tid; n < NN; n += 384) {
        float p[HH];
#pragma unroll
        for (int h = 0; h < HH; h++) p[h] = sm[h][n];
#pragma unroll
        for (int g = 0; g < HH; g++) {
            float o = bls[g];
#pragma unroll
            for (int h = 0; h < HH; h++) o += wls[g * HH + h] * p[h];
            sm[g][n] = o;
        }
    }
    __syncthreads();

    {
        const int h = wid;
        float mx = -1e30f;
        for (int n = lane; n < NN; n += 32) mx = fmaxf(mx, sm[h][n]);
#pragma unroll
        for (int o = 16; o > 0; o >>= 1) mx = fmaxf(mx, __shfl_xor_sync(0xffffffffu, mx, o));
        float sum = 0.f;
        for (int n = lane; n < NN; n += 32) {
            float e = __expf(sm[h][n] - mx);
            sm[h][n] = e; sum += e;
        }
#pragma unroll
        for (int o = 16; o > 0; o >>= 1) sum += __shfl_xor_sync(0xffffffffu, sum, o);
        float inv = 1.f / sum;
        for (int n = lane; n < NN; n += 32) sm[h][n] *= inv;
    }
    __syncthreads();

    for (int n2 = tid; n2 < NN / 2; n2 += 384) {
        int n = n2 * 2;
        float p0[HH], p1[HH];
#pragma unroll
        for (int h = 0; h < HH; h++) { p0[h] = sm[h][n]; p1[h] = sm[h][n + 1]; }
#pragma unroll
        for (int g = 0; g < HH; g++) {
            float o0 = bws[g], o1 = bws[g];
#pragma unroll
            for (int h = 0; h < HH; h++) { o0 += wws[g * HH + h] * p0[h]; o1 += wws[g * HH + h] * p1[h]; }
            size_t idx = ((size_t)(b * HH + g) * NN + m) * NN + n;
            *reinterpret_cast<__half2*>(g_a2f + idx) = __floats2half2_rn(o0, o1);
        }
    }
}

// ============================ O = attn2 @ V per (b,h)  (fp16 1-MMA) ============================
// grid (5, 192). K = 576.
__global__ __launch_bounds__(256, 3) void av_mma() {
    extern __shared__ char smem[];
    u32 sb = smem_u32(smem);
    const int m0 = blockIdx.x * 128, bh = blockIdx.y;
    float acc[2][4][4];
#pragma unroll
    for (int i = 0; i < 2; i++)
#pragma unroll
        for (int j = 0; j < 4; j++)
#pragma unroll
            for (int k = 0; k < 4; k++) acc[i][j][k] = 0.f;
    const size_t ab = (size_t)bh * NN * NN + (size_t)m0 * NN;
    const size_t bb = (size_t)bh * HDIM * NN;
    gemm_core_f16s<128, 64, 4, 2>(g_a2f + ab, NN, g_vtf + bb, NN, NN, sb, acc);
    const int tid = threadIdx.x, lane = tid & 31, wid = tid >> 5;
    const int wm = wid >> 1, wn = wid & 1;
    const int b = bh / HH, h = bh - b * HH;
#pragma unroll
    for (int mi = 0; mi < 2; mi++)
#pragma unroll
        for (int ni = 0; ni < 4; ni++) {
            int dc = wn * 32 + ni * 8 + (lane & 3) * 2;
#pragma unroll
            for (int hf = 0; hf < 2; hf++) {
                int m = m0 + wm * 32 + mi * 16 + (lane >> 2) + hf * 8;
                if (m < NN) {
                    size_t base = ((size_t)b * NN + m) * CC + h * HDIM + dc;
                    *reinterpret_cast<__half2*>(g_o1f + base) =
                        __floats2half2_rn(acc[mi][ni][hf * 2], acc[mi][ni][hf * 2 + 1]);
                }
            }
        }
}

// ============================ out = o1 @ Wproj^T + bias (fp16 2-MMA, BN=128) ============================
// grid (6, 72)
__global__ __launch_bounds__(256, 2) void proj_mma(const float* __restrict__ bias,
                                                   float* __restrict__ out) {
    extern __shared__ char smem[];
    u32 sb = smem_u32(smem);
    const int n0 = blockIdx.x * 128, m0 = blockIdx.y * 128;
    float acc[4][4][4];
#pragma unroll
    for (int i = 0; i < 4; i++)
#pragma unroll
        for (int j = 0; j < 4; j++)
#pragma unroll
            for (int k = 0; k < 4; k++) acc[i][j][k] = 0.f;
    gemm_core_f16<128, 128, 2, 4>(g_o1f + (size_t)m0 * CC, CC,
                                  g_wphf + (size_t)n0 * CC, g_wplf + (size_t)n0 * CC, CC,
                                  CC, sb, acc);
    const int tid = threadIdx.x, lane = tid & 31, wid = tid >> 5;
    const int wm = wid >> 2, wn = wid & 3;
#pragma unroll
    for (int mi = 0; mi < 4; mi++)
#pragma unroll
        for (int ni = 0; ni < 4; ni++) {
            int c = n0 + wn * 32 + ni * 8 + (lane & 3) * 2;
            float b0 = __ldg(&bias[c]), b1 = __ldg(&bias[c + 1]);
#pragma unroll
            for (int hf = 0; hf < 2; hf++) {
                int m = m0 + wm * 64 + mi * 16 + (lane >> 2) + hf * 8;
                *reinterpret_cast<float2*>(out + (size_t)m * CC + c) =
                    make_float2(acc[mi][ni][hf * 2] + b0, acc[mi][ni][hf * 2 + 1] + b1);
            }
        }
}

// ============================ launch ============================
extern "C" void kernel_launch(void* const* d_in, const int* in_sizes, int n_in,
                              void* d_out, int out_size) {
    const float* x     = (const float*)d_in[0];
    const float* Wqkv  = (const float*)d_in[1];
    const float* Wl    = (const float*)d_in[2];
    const float* bl    = (const float*)d_in[3];
    const float* Ww    = (const float*)d_in[4];
    const float* bw    = (const float*)d_in[5];
    const float* Wproj = (const float*)d_in[6];
    const float* bproj = (const float*)d_in[7];
    float* out = (float*)d_out;

    static bool attr_done = false;
    if (!attr_done) {
        cudaFuncSetAttribute(qkv_mma,   cudaFuncAttributeMaxDynamicSharedMemorySize, QKV_SMEM);
        cudaFuncSetAttribute(score_mma, cudaFuncAttributeMaxDynamicSharedMemorySize, SCORE_SMEM);
        cudaFuncSetAttribute(av_mma,    cudaFuncAttributeMaxDynamicSharedMemorySize, AV_SMEM);
        cudaFuncSetAttribute(proj_mma,  cudaFuncAttributeMaxDynamicSharedMemorySize, PROJ_SMEM);
        attr_done = true;
    }

    __half *xf, *wqhf, *wqlf, *wphf, *wplf;
    cudaGetSymbolAddress((void**)&xf, g_xf);
    cudaGetSymbolAddress((void**)&wqhf, g_wqhf); cudaGetSymbolAddress((void**)&wqlf, g_wqlf);
    cudaGetSymbolAddress((void**)&wphf, g_wphf); cudaGetSymbolAddress((void**)&wplf, g_wplf);

    split_f16s_kernel<<<(MTOT * CC / 4 + 255) / 256, 256>>>(x, xf, MTOT * CC);
    split_f16_kernel<<<(3 * CC * CC / 4 + 255) / 256, 256>>>(Wqkv, wqhf, wqlf, 3 * CC * CC);
    split_f16_kernel<<<(CC * CC / 4 + 255) / 256, 256>>>(Wproj, wphf, wplf, CC * CC);

    qkv_mma<<<dim3(18, 72), 256, QKV_SMEM>>>();
    transpose_v<<<dim3(18, 2, BB * HH), dim3(32, 8)>>>();
    score_mma<<<dim3(5, BB * HH), 256, SCORE_SMEM>>>();
    softmax_mix_kernel<<<MTOT, 384>>>(Wl, bl, Ww, bw);
    av_mma<<<dim3(5, BB * HH), 256, AV_SMEM>>>();
    proj_mma<<<dim3(6, 72), 256, PROJ_SMEM>>>(bproj, out);
}

// round 13
// speedup vs baseline: 1.2371x; 1.0251x over previous
#include <cuda_runtime.h>
#include <cuda_bf16.h>
#include <cuda_fp16.h>

// Talking-heads attention via mma.sync tensor cores (plain sm_100 ISA).
// v12: all four GEMMs on the fp16 reduced-MMA scheme.
//   qkv : x single fp16 x Wqkv fp16 hi/lo   -> 2 MMAs/k-step
//   score: q single fp16 x k fp16 hi/lo      -> 2 MMAs/k-step (3 CTAs/SM)
//   av  : attn2 single fp16 x V^T single fp16 -> 1 MMA/k-step
//   proj: o1 single fp16 x Wproj fp16 hi/lo  -> 2 MMAs/k-step

#define BB 16
#define NN 576
#define CC 768
#define HH 12
#define HDIM 64
#define MTOT (BB * NN)
#define SCALE 0.125f
#define ATT ((size_t)BB * HH * NN * NN)
#define QKE (BB * HH * NN * HDIM)

typedef unsigned int u32;

// ============================ PTX helpers ============================
__device__ __forceinline__ u32 smem_u32(const void* p) {
    u32 a;
    asm("{ .reg .u64 t; cvta.to.shared.u64 t, %1; cvt.u32.u64 %0, t; }" : "=r"(a) : "l"(p));
    return a;
}
__device__ __forceinline__ void cp16(u32 dst, const void* src) {
    asm volatile("cp.async.cg.shared.global [%0], [%1], 16;" :: "r"(dst), "l"(src));
}
__device__ __forceinline__ void cp_commit() {
    asm volatile("cp.async.commit_group;" ::: "memory");
}
template <int N>
__device__ __forceinline__ void cp_wait() {
    asm volatile("cp.async.wait_group %0;" :: "n"(N) : "memory");
}
__device__ __forceinline__ void ldm_x4(u32 a, u32& r0, u32& r1, u32& r2, u32& r3) {
    asm volatile("ldmatrix.sync.aligned.m8n8.x4.shared.b16 {%0,%1,%2,%3}, [%4];"
                 : "=r"(r0), "=r"(r1), "=r"(r2), "=r"(r3) : "r"(a));
}
__device__ __forceinline__ void mma_f16(float* d, const u32* a, const u32* b) {
    asm volatile("mma.sync.aligned.m16n8k16.row.col.f32.f16.f16.f32 "
                 "{%0,%1,%2,%3}, {%4,%5,%6,%7}, {%8,%9}, {%0,%1,%2,%3};"
                 : "+f"(d[0]), "+f"(d[1]), "+f"(d[2]), "+f"(d[3])
                 : "r"(a[0]), "r"(a[1]), "r"(a[2]), "r"(a[3]), "r"(b[0]), "r"(b[1]));
}

// ============================ scratch (16B-aligned; generous pads) ============================
__device__ __align__(16) __half g_xf[MTOT * CC];                          // x single fp16
__device__ __align__(16) __half g_wqhf[3 * CC * CC], g_wqlf[3 * CC * CC]; // Wqkv fp16 hi/lo
__device__ __align__(16) __half g_qf[QKE + 128 * HDIM];                   // q single fp16 (pre-scaled)
__device__ __align__(16) __half g_khf[QKE + 128 * HDIM], g_klf[QKE + 128 * HDIM]; // k fp16 hi/lo
__device__ __align__(16) __half g_vf[QKE];                                // v single fp16
__device__ __align__(16) __half g_vtf[QKE];                               // v^T single fp16
__device__ __align__(16) float g_attn[ATT];
__device__ __align__(16) __half g_a2f[ATT + 128 * NN];                    // attn2 single fp16
__device__ __align__(16) __half g_o1f[MTOT * CC];                         // o1 single fp16
__device__ __align__(16) __half g_wphf[CC * CC], g_wplf[CC * CC];         // Wproj fp16 hi/lo

__device__ __forceinline__ u32 pack_hi_lo_f16(float f0, float f1, u32& lo_out) {
    __half h0 = __float2half(f0);
    __half h1 = __float2half(f1);
    __half l0 = __float2half(f0 - __half2float(h0));
    __half l1 = __float2half(f1 - __half2float(h1));
    u32 hw = ((u32)__half_as_ushort(h1) << 16) | __half_as_ushort(h0);
    lo_out = ((u32)__half_as_ushort(l1) << 16) | __half_as_ushort(l0);
    return hw;
}

// ============================ fp16 single-A / pair-B GEMM core (3-stage, 2-MMA) ============================
template <int BM, int BN, int TMW, int TNW>
__device__ __forceinline__ void gemm_core_f16(
    const __half* __restrict__ Af, int lda,
    const __half* __restrict__ Bh, const __half* __restrict__ Bl, int ldb,
    int K, u32 sb, float (*acc)[4][4]) {
    constexpr int MI = BM / TMW / 16;
    constexpr int NI = BN / TNW / 8;
    static_assert(NI == 4, "epilogue layout assumes NI==4");
    constexpr u32 OFF_BH = BM * 64;
    constexpr u32 OFF_BL = BM * 64 + BN * 64;
    constexpr u32 SS = (BM + 2 * BN) * 64;
    const int tid = threadIdx.x;
    const int lane = tid & 31, wid = tid >> 5;
    const int wrow = (wid / TNW) * (BM / TMW);
    const int wcol = (wid % TNW) * (BN / TNW);
    const int NK = K >> 5;

    auto issue = [&](int kt) {
        const u32 st = sb + (u32)(kt % 3) * SS;
        const int k0 = kt << 5;
#pragma unroll
        for (int i = tid; i < BM * 4; i += 256) {
            int r = i >> 2, c = i & 3;
            u32 doff = (u32)(r * 64 + ((c ^ ((r >> 1) & 3)) << 4));
            cp16(st + doff, Af + (size_t)r * lda + k0 + c * 8);
        }
#pragma unroll
        for (int i = tid; i < BN * 4; i += 256) {
            int r = i >> 2, c = i & 3;
            u32 doff = (u32)(r * 64 + ((c ^ ((r >> 1) & 3)) << 4));
            cp16(st + OFF_BH + doff, Bh + (size_t)r * ldb + k0 + c * 8);
            cp16(st + OFF_BL + doff, Bl + (size_t)r * ldb + k0 + c * 8);
        }
        cp_commit();
    };

    issue(0);
    if (NK > 1) issue(1);
    for (int kt = 0; kt < NK; kt++) {
        if (kt + 1 < NK) cp_wait<1>();
        else             cp_wait<0>();
        __syncthreads();
        if (kt + 2 < NK) issue(kt + 2);
        const u32 st = sb + (u32)(kt % 3) * SS;
#pragma unroll
        for (int ks = 0; ks < 2; ks++) {
            u32 bhf[NI][2], blf[NI][2];
            {
                const int kc = ks * 2 + ((lane >> 3) & 1);
                const int rb = wcol + ((lane >> 4) << 3) + (lane & 7);
#pragma unroll
                for (int ni = 0; ni < NI; ni += 2) {
                    int r = rb + ni * 8;
                    u32 swz = (u32)(r * 64 + ((kc ^ ((r >> 1) & 3)) << 4));
                    ldm_x4(st + OFF_BH + swz, bhf[ni][0], bhf[ni][1], bhf[ni + 1][0], bhf[ni + 1][1]);
                    ldm_x4(st + OFF_BL + swz, blf[ni][0], blf[ni][1], blf[ni + 1][0], blf[ni + 1][1]);
                }
            }
            const int kcA = ks * 2 + (lane >> 4);
#pragma unroll
            for (int mi = 0; mi < MI; mi++) {
                int r = wrow + mi * 16 + (lane & 15);
                u32 a = st + (u32)(r * 64 + ((kcA ^ ((r >> 1) & 3)) << 4));
                u32 af[4];
                ldm_x4(a, af[0], af[1], af[2], af[3]);
#pragma unroll
                for (int ni = 0; ni < NI; ni++) mma_f16(acc[mi][ni], af, bhf[ni]);
#pragma unroll
                for (int ni = 0; ni < NI; ni++) mma_f16(acc[mi][ni], af, blf[ni]);
            }
        }
    }
}

// ============================ fp16 single/single GEMM core (3-stage, 1-MMA) ============================
template <int BM, int BN, int TMW, int TNW>
__device__ __forceinline__ void gemm_core_f16s(
    const __half* __restrict__ Af, int lda,
    const __half* __restrict__ Bf, int ldb,
    int K, u32 sb, float (*acc)[4][4]) {
    constexpr int MI = BM / TMW / 16;
    constexpr int NI = BN / TNW / 8;
    static_assert(NI == 4, "epilogue layout assumes NI==4");
    constexpr u32 OFF_B = BM * 64;
    constexpr u32 SS = (BM + BN) * 64;
    const int tid = threadIdx.x;
    const int lane = tid & 31, wid = tid >> 5;
    const int wrow = (wid / TNW) * (BM / TMW);
    const int wcol = (wid % TNW) * (BN / TNW);
    const int NK = K >> 5;

    auto issue = [&](int kt) {
        const u32 st = sb + (u32)(kt % 3) * SS;
        const int k0 = kt << 5;
#pragma unroll
        for (int i = tid; i < BM * 4; i += 256) {
            int r = i >> 2, c = i & 3;
            u32 doff = (u32)(r * 64 + ((c ^ ((r >> 1) & 3)) << 4));
            cp16(st + doff, Af + (size_t)r * lda + k0 + c * 8);
        }
#pragma unroll
        for (int i = tid; i < BN * 4; i += 256) {
            int r = i >> 2, c = i & 3;
            u32 doff = (u32)(r * 64 + ((c ^ ((r >> 1) & 3)) << 4));
            cp16(st + OFF_B + doff, Bf + (size_t)r * ldb + k0 + c * 8);
        }
        cp_commit();
    };

    issue(0);
    if (NK > 1) issue(1);
    for (int kt = 0; kt < NK; kt++) {
        if (kt + 1 < NK) cp_wait<1>();
        else             cp_wait<0>();
        __syncthreads();
        if (kt + 2 < NK) issue(kt + 2);
        const u32 st = sb + (u32)(kt % 3) * SS;
#pragma unroll
        for (int ks = 0; ks < 2; ks++) {
            u32 bf[NI][2];
            {
                const int kc = ks * 2 + ((lane >> 3) & 1);
                const int rb = wcol + ((lane >> 4) << 3) + (lane & 7);
#pragma unroll
                for (int ni = 0; ni < NI; ni += 2) {
                    int r = rb + ni * 8;
                    u32 swz = (u32)(r * 64 + ((kc ^ ((r >> 1) & 3)) << 4));
                    ldm_x4(st + OFF_B + swz, bf[ni][0], bf[ni][1], bf[ni + 1][0], bf[ni + 1][1]);
                }
            }
            const int kcA = ks * 2 + (lane >> 4);
#pragma unroll
            for (int mi = 0; mi < MI; mi++) {
                int r = wrow + mi * 16 + (lane & 15);
                u32 a = st + (u32)(r * 64 + ((kcA ^ ((r >> 1) & 3)) << 4));
                u32 af[4];
                ldm_x4(a, af[0], af[1], af[2], af[3]);
#pragma unroll
                for (int ni = 0; ni < NI; ni++) mma_f16(acc[mi][ni], af, bf[ni]);
            }
        }
    }
}

#define QKV_SMEM   73728   // 3 x 24576 (f16: A 8K + B 2x8K)
#define SCORE_SMEM 65536   // A 16K (single) + 3 x 16384 (K hi+lo)
#define AV_SMEM    36864   // 3 x 12288 (f16s: A 8K + B 4K)
#define PROJ_SMEM  73728   // 3 x 24576

// ============================ fp32 -> fp16 single ============================
__global__ __launch_bounds__(256) void split_f16s_kernel(const float* __restrict__ in,
                                                         __half* __restrict__ o, int n) {
    int i = (blockIdx.x * 256 + threadIdx.x) * 4;
    if (i >= n) return;
    float4 v = *reinterpret_cast<const float4*>(in + i);
    __half2 a = __floats2half2_rn(v.x, v.y);
    __half2 b = __floats2half2_rn(v.z, v.w);
    *reinterpret_cast<uint2*>(o + i) = make_uint2(*(u32*)&a, *(u32*)&b);
}

// ============================ fp32 -> fp16 hi/lo split ============================
__global__ __launch_bounds__(256) void split_f16_kernel(const float* __restrict__ in,
                                                        __half* __restrict__ hi,
                                                        __half* __restrict__ lo, int n) {
    int i = (blockIdx.x * 256 + threadIdx.x) * 4;
    if (i >= n) return;
    float4 v = *reinterpret_cast<const float4*>(in + i);
    float f[4] = {v.x, v.y, v.z, v.w};
    __half h[4], l[4];
#pragma unroll
    for (int j = 0; j < 4; j++) {
        h[j] = __float2half(f[j]);
        l[j] = __float2half(f[j] - __half2float(h[j]));
    }
    *reinterpret_cast<uint2*>(hi + i) = *reinterpret_cast<uint2*>(h);
    *reinterpret_cast<uint2*>(lo + i) = *reinterpret_cast<uint2*>(l);
}

// ============================ QKV GEMM + scatter (f16 2-MMA, BN=128) ============================
// grid (18, 72)
__global__ __launch_bounds__(256, 2) void qkv_mma() {
    extern __shared__ char smem[];
    u32 sb = smem_u32(smem);
    const int n0 = blockIdx.x * 128, m0 = blockIdx.y * 128;
    float acc[4][4][4];
#pragma unroll
    for (int i = 0; i < 4; i++)
#pragma unroll
        for (int j = 0; j < 4; j++)
#pragma unroll
            for (int k = 0; k < 4; k++) acc[i][j][k] = 0.f;
    gemm_core_f16<128, 128, 2, 4>(g_xf + (size_t)m0 * CC, CC,
                                  g_wqhf + (size_t)n0 * CC, g_wqlf + (size_t)n0 * CC, CC,
                                  CC, sb, acc);
    const int tid = threadIdx.x, lane = tid & 31, wid = tid >> 5;
    const int wm = wid >> 2, wn = wid & 3;
#pragma unroll
    for (int mi = 0; mi < 4; mi++)
#pragma unroll
        for (int ni = 0; ni < 4; ni++) {
            int c = n0 + wn * 32 + ni * 8 + (lane & 3) * 2;
            int t = c / CC, rc = c - t * CC, h = rc >> 6, d0 = rc & 63;
#pragma unroll
            for (int hf = 0; hf < 2; hf++) {
                int m = m0 + wm * 64 + mi * 16 + (lane >> 2) + hf * 8;
                int b = m / NN, ntok = m - b * NN;
                size_t base = ((size_t)(b * HH + h) * NN + ntok) * HDIM + d0;
                float f0 = acc[mi][ni][hf * 2], f1 = acc[mi][ni][hf * 2 + 1];
                if (t == 0) {          // q: single fp16, pre-scaled
                    *reinterpret_cast<__half2*>(g_qf + base) =
                        __floats2half2_rn(f0 * SCALE, f1 * SCALE);
                } else if (t == 2) {   // v: single fp16
                    *reinterpret_cast<__half2*>(g_vf + base) = __floats2half2_rn(f0, f1);
                } else {               // k: fp16 hi/lo pair
                    u32 lw, hw = pack_hi_lo_f16(f0, f1, lw);
                    *reinterpret_cast<u32*>(g_khf + base) = hw;
                    *reinterpret_cast<u32*>(g_klf + base) = lw;
                }
            }
        }
}

// ============================ transpose V -> vT[d][n] (single fp16) ============================
__global__ __launch_bounds__(256) void transpose_v() {
    __shared__ __half tf[32][34];
    int n0 = blockIdx.x * 32, d0 = blockIdx.y * 32, bh = blockIdx.z;
    int tx = threadIdx.x, ty = threadIdx.y;
#pragma unroll
    for (int i = 0; i < 4; i++) {
        int n = n0 + ty + i * 8;
        tf[ty + i * 8][tx] = g_vf[((size_t)bh * NN + n) * HDIM + d0 + tx];
    }
    __syncthreads();
#pragma unroll
    for (int i = 0; i < 4; i++) {
        int d = d0 + ty + i * 8;
        g_vtf[((size_t)bh * HDIM + d) * NN + n0 + tx] = tf[tx][ty + i * 8];
    }
}

// ============================ score: persistent-Q n-loop kernel (fp16 2-MMA) ============================
// grid (5, 192). Q tile (single fp16) resident; K hi/lo tiles stream through a 3-stage ring.
__global__ __launch_bounds__(256, 3) void score_mma() {
    extern __shared__ char smem[];
    u32 sb = smem_u32(smem);
    const u32 A_F = 0, RING = 16384;   // K stage: Kh 8192 + Kl 8192
    const int m0 = blockIdx.x * 128, bhi = blockIdx.y;
    const int tid = threadIdx.x, lane = tid & 31, wid = tid >> 5;
    const int wm = wid >> 1, wn = wid & 1;
    const int wrow = wm * 32, wcol = wn * 32;

    const __half* Qf = g_qf + ((size_t)bhi * NN + m0) * HDIM;
    const __half* Kh = g_khf + (size_t)bhi * NN * HDIM;
    const __half* Kl = g_klf + (size_t)bhi * NN * HDIM;

    // Q tile (128 x 64 fp16, two 32-col subtiles). Rows beyond 576 hit the pad.
#pragma unroll
    for (int i = tid; i < 128 * 8; i += 256) {
        int r = i >> 3, cc = i & 7, kt = cc >> 2, c = cc & 3;
        u32 doff = (u32)(kt * 8192 + r * 64 + ((c ^ ((r >> 1) & 3)) << 4));
        cp16(sb + A_F + doff, Qf + (size_t)r * HDIM + kt * 32 + c * 8);
    }
    cp_commit();

    auto issueB = [&](int nt) {
        const u32 st = sb + RING + (u32)(nt % 3) * 16384;
#pragma unroll
        for (int i = tid; i < 64 * 8; i += 256) {
            int r = i >> 3, cc = i & 7, kt = cc >> 2, c = cc & 3;
            u32 doff = (u32)(kt * 4096 + r * 64 + ((c ^ ((r >> 1) & 3)) << 4));
            size_t so = (size_t)(nt * 64 + r) * HDIM + kt * 32 + c * 8;
            cp16(st + doff, Kh + so);
            cp16(st + 8192 + doff, Kl + so);
        }
        cp_commit();
    };
    issueB(0); issueB(1);

    float* outb = g_attn + (size_t)bhi * NN * NN;
    for (int nt = 0; nt < 9; nt++) {
        if (nt < 8) cp_wait<1>();
        else        cp_wait<0>();
        __syncthreads();
        if (nt + 2 < 9) issueB(nt + 2);
        const u32 st = sb + RING + (u32)(nt % 3) * 16384;

        float acc[2][4][4];
#pragma unroll
        for (int i = 0; i < 2; i++)
#pragma unroll
            for (int j = 0; j < 4; j++)
#pragma unroll
                for (int k = 0; k < 4; k++) acc[i][j][k] = 0.f;

#pragma unroll
        for (int kt = 0; kt < 2; kt++)
#pragma unroll
            for (int ks = 0; ks < 2; ks++) {
                u32 bhf[4][2], blf[4][2];
                {
                    const int kc = ks * 2 + ((lane >> 3) & 1);
                    const int rb = wcol + ((lane >> 4) << 3) + (lane & 7);
#pragma unroll
                    for (int ni = 0; ni < 4; ni += 2) {
                        int r = rb + ni * 8;
                        u32 swz = (u32)(kt * 4096 + r * 64 + ((kc ^ ((r >> 1) & 3)) << 4));
                        ldm_x4(st + swz, bhf[ni][0], bhf[ni][1], bhf[ni + 1][0], bhf[ni + 1][1]);
                        ldm_x4(st + 8192 + swz, blf[ni][0], blf[ni][1], blf[ni + 1][0], blf[ni + 1][1]);
                    }
                }
                const int kcA = ks * 2 + (lane >> 4);
#pragma unroll
                for (int mi = 0; mi < 2; mi++) {
                    int r = wrow + mi * 16 + (lane & 15);
                    u32 aoff = (u32)(kt * 8192 + r * 64 + ((kcA ^ ((r >> 1) & 3)) << 4));
                    u32 af[4];
                    ldm_x4(sb + A_F + aoff, af[0], af[1], af[2], af[3]);
#pragma unroll
                    for (int ni = 0; ni < 4; ni++) mma_f16(acc[mi][ni], af, bhf[ni]);
#pragma unroll
                    for (int ni = 0; ni < 4; ni++) mma_f16(acc[mi][ni], af, blf[ni]);
                }
            }

        const int n0 = nt * 64;
#pragma unroll
        for (int mi = 0; mi < 2; mi++)
#pragma unroll
            for (int ni = 0; ni < 4; ni++) {
                int c = n0 + wn * 32 + ni * 8 + (lane & 3) * 2;
#pragma unroll
                for (int hf = 0; hf < 2; hf++) {
                    int m = m0 + wm * 32 + mi * 16 + (lane >> 2) + hf * 8;
                    if (m < NN)
                        *reinterpret_cast<float2*>(outb + (size_t)m * NN + c) =
                            make_float2(acc[mi][ni][hf * 2], acc[mi][ni][hf * 2 + 1]);
                }
            }
    }
}

// ============================ softmax + both mixes; attn2 out = single fp16 ============================
__global__ __launch_bounds__(384) void softmax_mix_kernel(const float* __restrict__ Wl,
                                                          const float* __restrict__ bl,
                                                          const float* __restrict__ Ww,
                                                          const float* __restrict__ bw) {
    __shared__ __align__(16) float sm[HH][NN];
    __shared__ float wls[HH * HH], bls[HH], wws[HH * HH], bws[HH];
    const int bm = blockIdx.x;
    const int b = bm / NN, m = bm % NN;
    const int tid = threadIdx.x, lane = tid & 31, wid = tid >> 5;

    if (tid < HH * HH) { wls[tid] = Wl[tid]; wws[tid] = Ww[tid]; }
    if (tid < HH) { bls[tid] = bl[tid]; bws[tid] = bw[tid]; }

    for (int idx = tid; idx < HH * NN / 4; idx += 384) {
        int h = idx / (NN / 4), n4 = idx - h * (NN / 4);
        float4 v = *reinterpret_cast<const float4*>(
            &g_attn[((size_t)(b * HH + h) * NN + m) * NN + n4 * 4]);
        *reinterpret_cast<float4*>(&sm[h][n4 * 4]) = v;
    }
    __syncthreads();

    for (int n = tid; n < NN; n += 384) {
        float p[HH];
#pragma unroll
        for (int h = 0; h < HH; h++) p[h] = sm[h][n];
#pragma unroll
        for (int g = 0; g < HH; g++) {
            float o = bls[g];
#pragma unroll
            for (int h = 0; h < HH; h++) o += wls[g * HH + h] * p[h];
            sm[g][n] = o;
        }
    }
    __syncthreads();

    {
        const int h = wid;
        float mx = -1e30f;
        for (int n = lane; n < NN; n += 32) mx = fmaxf(mx, sm[h][n]);
#pragma unroll
        for (int o = 16; o > 0; o >>= 1) mx = fmaxf(mx, __shfl_xor_sync(0xffffffffu, mx, o));
        float sum = 0.f;
        for (int n = lane; n < NN; n += 32) {
            float e = __expf(sm[h][n] - mx);
            sm[h][n] = e; sum += e;
        }
#pragma unroll
        for (int o = 16; o > 0; o >>= 1) sum += __shfl_xor_sync(0xffffffffu, sum, o);
        float inv = 1.f / sum;
        for (int n = lane; n < NN; n += 32) sm[h][n] *= inv;
    }
    __syncthreads();

    for (int n2 = tid; n2 < NN / 2; n2 += 384) {
        int n = n2 * 2;
        float p0[HH], p1[HH];
#pragma unroll
        for (int h = 0; h < HH; h++) { p0[h] = sm[h][n]; p1[h] = sm[h][n + 1]; }
#pragma unroll
        for (int g = 0; g < HH; g++) {
            float o0 = bws[g], o1 = bws[g];
#pragma unroll
            for (int h = 0; h < HH; h++) { o0 += wws[g * HH + h] * p0[h]; o1 += wws[g * HH + h] * p1[h]; }
            size_t idx = ((size_t)(b * HH + g) * NN + m) * NN + n;
            *reinterpret_cast<__half2*>(g_a2f + idx) = __floats2half2_rn(o0, o1);
        }
    }
}

// ============================ O = attn2 @ V per (b,h)  (fp16 1-MMA) ============================
// grid (5, 192). K = 576.
__global__ __launch_bounds__(256, 3) void av_mma() {
    extern __shared__ char smem[];
    u32 sb = smem_u32(smem);
    const int m0 = blockIdx.x * 128, bh = blockIdx.y;
    float acc[2][4][4];
#pragma unroll
    for (int i = 0; i < 2; i++)
#pragma unroll
        for (int j = 0; j < 4; j++)
#pragma unroll
            for (int k = 0; k < 4; k++) acc[i][j][k] = 0.f;
    const size_t ab = (size_t)bh * NN * NN + (size_t)m0 * NN;
    const size_t bb = (size_t)bh * HDIM * NN;
    gemm_core_f16s<128, 64, 4, 2>(g_a2f + ab, NN, g_vtf + bb, NN, NN, sb, acc);
    const int tid = threadIdx.x, lane = tid & 31, wid = tid >> 5;
    const int wm = wid >> 1, wn = wid & 1;
    const int b = bh / HH, h = bh - b * HH;
#pragma unroll
    for (int mi = 0; mi < 2; mi++)
#pragma unroll
        for (int ni = 0; ni < 4; ni++) {
            int dc = wn * 32 + ni * 8 + (lane & 3) * 2;
#pragma unroll
            for (int hf = 0; hf < 2; hf++) {
                int m = m0 + wm * 32 + mi * 16 + (lane >> 2) + hf * 8;
                if (m < NN) {
                    size_t base = ((size_t)b * NN + m) * CC + h * HDIM + dc;
                    *reinterpret_cast<__half2*>(g_o1f + base) =
                        __floats2half2_rn(acc[mi][ni][hf * 2], acc[mi][ni][hf * 2 + 1]);
                }
            }
        }
}

// ============================ out = o1 @ Wproj^T + bias (fp16 2-MMA, BN=128) ============================
// grid (6, 72)
__global__ __launch_bounds__(256, 2) void proj_mma(const float* __restrict__ bias,
                                                   float* __restrict__ out) {
    extern __shared__ char smem[];
    u32 sb = smem_u32(smem);
    const int n0 = blockIdx.x * 128, m0 = blockIdx.y * 128;
    float acc[4][4][4];
#pragma unroll
    for (int i = 0; i < 4; i++)
#pragma unroll
        for (int j = 0; j < 4; j++)
#pragma unroll
            for (int k = 0; k < 4; k++) acc[i][j][k] = 0.f;
    gemm_core_f16<128, 128, 2, 4>(g_o1f + (size_t)m0 * CC, CC,
                                  g_wphf + (size_t)n0 * CC, g_wplf + (size_t)n0 * CC, CC,
                                  CC, sb, acc);
    const int tid = threadIdx.x, lane = tid & 31, wid = tid >> 5;
    const int wm = wid >> 2, wn = wid & 3;
#pragma unroll
    for (int mi = 0; mi < 4; mi++)
#pragma unroll
        for (int ni = 0; ni < 4; ni++) {
            int c = n0 + wn * 32 + ni * 8 + (lane & 3) * 2;
            float b0 = __ldg(&bias[c]), b1 = __ldg(&bias[c + 1]);
#pragma unroll
            for (int hf = 0; hf < 2; hf++) {
                int m = m0 + wm * 64 + mi * 16 + (lane >> 2) + hf * 8;
                *reinterpret_cast<float2*>(out + (size_t)m * CC + c) =
                    make_float2(acc[mi][ni][hf * 2] + b0, acc[mi][ni][hf * 2 + 1] + b1);
            }
        }
}

// ============================ launch ============================
extern "C" void kernel_launch(void* const* d_in, const int* in_sizes, int n_in,
                              void* d_out, int out_size) {
    const float* x     = (const float*)d_in[0];
    const float* Wqkv  = (const float*)d_in[1];
    const float* Wl    = (const float*)d_in[2];
    const float* bl    = (const float*)d_in[3];
    const float* Ww    = (const float*)d_in[4];
    const float* bw    = (const float*)d_in[5];
    const float* Wproj = (const float*)d_in[6];
    const float* bproj = (const float*)d_in[7];
    float* out = (float*)d_out;

    static bool attr_done = false;
    if (!attr_done) {
        cudaFuncSetAttribute(qkv_mma,   cudaFuncAttributeMaxDynamicSharedMemorySize, QKV_SMEM);
        cudaFuncSetAttribute(score_mma, cudaFuncAttributeMaxDynamicSharedMemorySize, SCORE_SMEM);
        cudaFuncSetAttribute(av_mma,    cudaFuncAttributeMaxDynamicSharedMemorySize, AV_SMEM);
        cudaFuncSetAttribute(proj_mma,  cudaFuncAttributeMaxDynamicSharedMemorySize, PROJ_SMEM);
        attr_done = true;
    }

    __half *xf, *wqhf, *wqlf, *wphf, *wplf;
    cudaGetSymbolAddress((void**)&xf, g_xf);
    cudaGetSymbolAddress((void**)&wqhf, g_wqhf); cudaGetSymbolAddress((void**)&wqlf, g_wqlf);
    cudaGetSymbolAddress((void**)&wphf, g_wphf); cudaGetSymbolAddress((void**)&wplf, g_wplf);

    split_f16s_kernel<<<(MTOT * CC / 4 + 255) / 256, 256>>>(x, xf, MTOT * CC);
    split_f16_kernel<<<(3 * CC * CC / 4 + 255) / 256, 256>>>(Wqkv, wqhf, wqlf, 3 * CC * CC);
    split_f16_kernel<<<(CC * CC / 4 + 255) / 256, 256>>>(Wproj, wphf, wplf, CC * CC);

    qkv_mma<<<dim3(18, 72), 256, QKV_SMEM>>>();
    transpose_v<<<dim3(18, 2, BB * HH), dim3(32, 8)>>>();
    score_mma<<<dim3(5, BB * HH), 256, SCORE_SMEM>>>();
    softmax_mix_kernel<<<MTOT, 384>>>(Wl, bl, Ww, bw);
    av_mma<<<dim3(5, BB * HH), 256, AV_SMEM>>>();
    proj_mma<<<dim3(6, 72), 256, PROJ_SMEM>>>(bproj, out);
}

// round 14
// speedup vs baseline: 1.3734x; 1.1102x over previous
#include <cuda_runtime.h>
#include <cuda_bf16.h>
#include <cuda_fp16.h>

// Talking-heads attention via mma.sync tensor cores (plain sm_100 ISA).
// v13: fp16 end-to-end intermediates.
//   qkv : x f16 x Wqkv f16 hi/lo  -> 2 MMAs/k-step; q,k,v all single f16 out
//   score: q f16 x k f16          -> 1 MMA/k-step; scores stored f16
//   av  : attn2 f16 x V^T f16     -> 1 MMA/k-step
//   proj: o1 f16 x Wproj f16 hi/lo -> 2 MMAs/k-step

#define BB 16
#define NN 576
#define CC 768
#define HH 12
#define HDIM 64
#define MTOT (BB * NN)
#define SCALE 0.125f
#define ATT ((size_t)BB * HH * NN * NN)
#define QKE (BB * HH * NN * HDIM)

typedef unsigned int u32;

// ============================ PTX helpers ============================
__device__ __forceinline__ u32 smem_u32(const void* p) {
    u32 a;
    asm("{ .reg .u64 t; cvta.to.shared.u64 t, %1; cvt.u32.u64 %0, t; }" : "=r"(a) : "l"(p));
    return a;
}
__device__ __forceinline__ void cp16(u32 dst, const void* src) {
    asm volatile("cp.async.cg.shared.global [%0], [%1], 16;" :: "r"(dst), "l"(src));
}
__device__ __forceinline__ void cp_commit() {
    asm volatile("cp.async.commit_group;" ::: "memory");
}
template <int N>
__device__ __forceinline__ void cp_wait() {
    asm volatile("cp.async.wait_group %0;" :: "n"(N) : "memory");
}
__device__ __forceinline__ void ldm_x4(u32 a, u32& r0, u32& r1, u32& r2, u32& r3) {
    asm volatile("ldmatrix.sync.aligned.m8n8.x4.shared.b16 {%0,%1,%2,%3}, [%4];"
                 : "=r"(r0), "=r"(r1), "=r"(r2), "=r"(r3) : "r"(a));
}
__device__ __forceinline__ void mma_f16(float* d, const u32* a, const u32* b) {
    asm volatile("mma.sync.aligned.m16n8k16.row.col.f32.f16.f16.f32 "
                 "{%0,%1,%2,%3}, {%4,%5,%6,%7}, {%8,%9}, {%0,%1,%2,%3};"
                 : "+f"(d[0]), "+f"(d[1]), "+f"(d[2]), "+f"(d[3])
                 : "r"(a[0]), "r"(a[1]), "r"(a[2]), "r"(a[3]), "r"(b[0]), "r"(b[1]));
}

// ============================ scratch (16B-aligned; generous pads) ============================
__device__ __align__(16) __half g_xf[MTOT * CC];                          // x single fp16
__device__ __align__(16) __half g_wqhf[3 * CC * CC], g_wqlf[3 * CC * CC]; // Wqkv fp16 hi/lo
__device__ __align__(16) __half g_qf[QKE + 128 * HDIM];                   // q f16 (pre-scaled)
__device__ __align__(16) __half g_kf[QKE + 128 * HDIM];                   // k f16
__device__ __align__(16) __half g_vf[QKE];                                // v f16
__device__ __align__(16) __half g_vtf[QKE];                               // v^T f16
__device__ __align__(16) __half g_attnf[ATT + 128 * NN];                  // raw scores f16
__device__ __align__(16) __half g_a2f[ATT + 128 * NN];                    // attn2 f16
__device__ __align__(16) __half g_o1f[MTOT * CC];                         // o1 f16
__device__ __align__(16) __half g_wphf[CC * CC], g_wplf[CC * CC];         // Wproj fp16 hi/lo

// ============================ fp16 single-A / pair-B GEMM core (3-stage, 2-MMA) ============================
template <int BM, int BN, int TMW, int TNW>
__device__ __forceinline__ void gemm_core_f16(
    const __half* __restrict__ Af, int lda,
    const __half* __restrict__ Bh, const __half* __restrict__ Bl, int ldb,
    int K, u32 sb, float (*acc)[4][4]) {
    constexpr int MI = BM / TMW / 16;
    constexpr int NI = BN / TNW / 8;
    static_assert(NI == 4, "epilogue layout assumes NI==4");
    constexpr u32 OFF_BH = BM * 64;
    constexpr u32 OFF_BL = BM * 64 + BN * 64;
    constexpr u32 SS = (BM + 2 * BN) * 64;
    const int tid = threadIdx.x;
    const int lane = tid & 31, wid = tid >> 5;
    const int wrow = (wid / TNW) * (BM / TMW);
    const int wcol = (wid % TNW) * (BN / TNW);
    const int NK = K >> 5;

    auto issue = [&](int kt) {
        const u32 st = sb + (u32)(kt % 3) * SS;
        const int k0 = kt << 5;
#pragma unroll
        for (int i = tid; i < BM * 4; i += 256) {
            int r = i >> 2, c = i & 3;
            u32 doff = (u32)(r * 64 + ((c ^ ((r >> 1) & 3)) << 4));
            cp16(st + doff, Af + (size_t)r * lda + k0 + c * 8);
        }
#pragma unroll
        for (int i = tid; i < BN * 4; i += 256) {
            int r = i >> 2, c = i & 3;
            u32 doff = (u32)(r * 64 + ((c ^ ((r >> 1) & 3)) << 4));
            cp16(st + OFF_BH + doff, Bh + (size_t)r * ldb + k0 + c * 8);
            cp16(st + OFF_BL + doff, Bl + (size_t)r * ldb + k0 + c * 8);
        }
        cp_commit();
    };

    issue(0);
    if (NK > 1) issue(1);
    for (int kt = 0; kt < NK; kt++) {
        if (kt + 1 < NK) cp_wait<1>();
        else             cp_wait<0>();
        __syncthreads();
        if (kt + 2 < NK) issue(kt + 2);
        const u32 st = sb + (u32)(kt % 3) * SS;
#pragma unroll
        for (int ks = 0; ks < 2; ks++) {
            u32 bhf[NI][2], blf[NI][2];
            {
                const int kc = ks * 2 + ((lane >> 3) & 1);
                const int rb = wcol + ((lane >> 4) << 3) + (lane & 7);
#pragma unroll
                for (int ni = 0; ni < NI; ni += 2) {
                    int r = rb + ni * 8;
                    u32 swz = (u32)(r * 64 + ((kc ^ ((r >> 1) & 3)) << 4));
                    ldm_x4(st + OFF_BH + swz, bhf[ni][0], bhf[ni][1], bhf[ni + 1][0], bhf[ni + 1][1]);
                    ldm_x4(st + OFF_BL + swz, blf[ni][0], blf[ni][1], blf[ni + 1][0], blf[ni + 1][1]);
                }
            }
            const int kcA = ks * 2 + (lane >> 4);
#pragma unroll
            for (int mi = 0; mi < MI; mi++) {
                int r = wrow + mi * 16 + (lane & 15);
                u32 a = st + (u32)(r * 64 + ((kcA ^ ((r >> 1) & 3)) << 4));
                u32 af[4];
                ldm_x4(a, af[0], af[1], af[2], af[3]);
#pragma unroll
                for (int ni = 0; ni < NI; ni++) mma_f16(acc[mi][ni], af, bhf[ni]);
#pragma unroll
                for (int ni = 0; ni < NI; ni++) mma_f16(acc[mi][ni], af, blf[ni]);
            }
        }
    }
}

// ============================ fp16 single/single GEMM core (3-stage, 1-MMA) ============================
template <int BM, int BN, int TMW, int TNW>
__device__ __forceinline__ void gemm_core_f16s(
    const __half* __restrict__ Af, int lda,
    const __half* __restrict__ Bf, int ldb,
    int K, u32 sb, float (*acc)[4][4]) {
    constexpr int MI = BM / TMW / 16;
    constexpr int NI = BN / TNW / 8;
    static_assert(NI == 4, "epilogue layout assumes NI==4");
    constexpr u32 OFF_B = BM * 64;
    constexpr u32 SS = (BM + BN) * 64;
    const int tid = threadIdx.x;
    const int lane = tid & 31, wid = tid >> 5;
    const int wrow = (wid / TNW) * (BM / TMW);
    const int wcol = (wid % TNW) * (BN / TNW);
    const int NK = K >> 5;

    auto issue = [&](int kt) {
        const u32 st = sb + (u32)(kt % 3) * SS;
        const int k0 = kt << 5;
#pragma unroll
        for (int i = tid; i < BM * 4; i += 256) {
            int r = i >> 2, c = i & 3;
            u32 doff = (u32)(r * 64 + ((c ^ ((r >> 1) & 3)) << 4));
            cp16(st + doff, Af + (size_t)r * lda + k0 + c * 8);
        }
#pragma unroll
        for (int i = tid; i < BN * 4; i += 256) {
            int r = i >> 2, c = i & 3;
            u32 doff = (u32)(r * 64 + ((c ^ ((r >> 1) & 3)) << 4));
            cp16(st + OFF_B + doff, Bf + (size_t)r * ldb + k0 + c * 8);
        }
        cp_commit();
    };

    issue(0);
    if (NK > 1) issue(1);
    for (int kt = 0; kt < NK; kt++) {
        if (kt + 1 < NK) cp_wait<1>();
        else             cp_wait<0>();
        __syncthreads();
        if (kt + 2 < NK) issue(kt + 2);
        const u32 st = sb + (u32)(kt % 3) * SS;
#pragma unroll
        for (int ks = 0; ks < 2; ks++) {
            u32 bf[NI][2];
            {
                const int kc = ks * 2 + ((lane >> 3) & 1);
                const int rb = wcol + ((lane >> 4) << 3) + (lane & 7);
#pragma unroll
                for (int ni = 0; ni < NI; ni += 2) {
                    int r = rb + ni * 8;
                    u32 swz = (u32)(r * 64 + ((kc ^ ((r >> 1) & 3)) << 4));
                    ldm_x4(st + OFF_B + swz, bf[ni][0], bf[ni][1], bf[ni + 1][0], bf[ni + 1][1]);
                }
            }
            const int kcA = ks * 2 + (lane >> 4);
#pragma unroll
            for (int mi = 0; mi < MI; mi++) {
                int r = wrow + mi * 16 + (lane & 15);
                u32 a = st + (u32)(r * 64 + ((kcA ^ ((r >> 1) & 3)) << 4));
                u32 af[4];
                ldm_x4(a, af[0], af[1], af[2], af[3]);
#pragma unroll
                for (int ni = 0; ni < NI; ni++) mma_f16(acc[mi][ni], af, bf[ni]);
            }
        }
    }
}

#define QKV_SMEM   73728   // 3 x 24576 (A 8K + B 2x8K)
#define SCORE_SMEM 40960   // A 16K (single) + 3 x 8192 (K single)
#define AV_SMEM    36864   // 3 x 12288 (A 8K + B 4K)
#define PROJ_SMEM  73728   // 3 x 24576

// ============================ fp32 -> fp16 single ============================
__global__ __launch_bounds__(256) void split_f16s_kernel(const float* __restrict__ in,
                                                         __half* __restrict__ o, int n) {
    int i = (blockIdx.x * 256 + threadIdx.x) * 4;
    if (i >= n) return;
    float4 v = *reinterpret_cast<const float4*>(in + i);
    __half2 a = __floats2half2_rn(v.x, v.y);
    __half2 b = __floats2half2_rn(v.z, v.w);
    *reinterpret_cast<uint2*>(o + i) = make_uint2(*(u32*)&a, *(u32*)&b);
}

// ============================ fp32 -> fp16 hi/lo split ============================
__global__ __launch_bounds__(256) void split_f16_kernel(const float* __restrict__ in,
                                                        __half* __restrict__ hi,
                                                        __half* __restrict__ lo, int n) {
    int i = (blockIdx.x * 256 + threadIdx.x) * 4;
    if (i >= n) return;
    float4 v = *reinterpret_cast<const float4*>(in + i);
    float f[4] = {v.x, v.y, v.z, v.w};
    __half h[4], l[4];
#pragma unroll
    for (int j = 0; j < 4; j++) {
        h[j] = __float2half(f[j]);
        l[j] = __float2half(f[j] - __half2float(h[j]));
    }
    *reinterpret_cast<uint2*>(hi + i) = *reinterpret_cast<uint2*>(h);
    *reinterpret_cast<uint2*>(lo + i) = *reinterpret_cast<uint2*>(l);
}

// ============================ QKV GEMM + scatter (f16 2-MMA, BN=128) ============================
// grid (18, 72)
__global__ __launch_bounds__(256, 2) void qkv_mma() {
    extern __shared__ char smem[];
    u32 sb = smem_u32(smem);
    const int n0 = blockIdx.x * 128, m0 = blockIdx.y * 128;
    float acc[4][4][4];
#pragma unroll
    for (int i = 0; i < 4; i++)
#pragma unroll
        for (int j = 0; j < 4; j++)
#pragma unroll
            for (int k = 0; k < 4; k++) acc[i][j][k] = 0.f;
    gemm_core_f16<128, 128, 2, 4>(g_xf + (size_t)m0 * CC, CC,
                                  g_wqhf + (size_t)n0 * CC, g_wqlf + (size_t)n0 * CC, CC,
                                  CC, sb, acc);
    const int tid = threadIdx.x, lane = tid & 31, wid = tid >> 5;
    const int wm = wid >> 2, wn = wid & 3;
#pragma unroll
    for (int mi = 0; mi < 4; mi++)
#pragma unroll
        for (int ni = 0; ni < 4; ni++) {
            int c = n0 + wn * 32 + ni * 8 + (lane & 3) * 2;
            int t = c / CC, rc = c - t * CC, h = rc >> 6, d0 = rc & 63;
            float sc = (t == 0) ? SCALE : 1.f;
            __half* dst = (t == 0) ? g_qf : (t == 1) ? g_kf : g_vf;
#pragma unroll
            for (int hf = 0; hf < 2; hf++) {
                int m = m0 + wm * 64 + mi * 16 + (lane >> 2) + hf * 8;
                int b = m / NN, ntok = m - b * NN;
                size_t base = ((size_t)(b * HH + h) * NN + ntok) * HDIM + d0;
                *reinterpret_cast<__half2*>(dst + base) =
                    __floats2half2_rn(acc[mi][ni][hf * 2] * sc, acc[mi][ni][hf * 2 + 1] * sc);
            }
        }
}

// ============================ transpose V -> vT[d][n] (single fp16) ============================
__global__ __launch_bounds__(256) void transpose_v() {
    __shared__ __half tf[32][34];
    int n0 = blockIdx.x * 32, d0 = blockIdx.y * 32, bh = blockIdx.z;
    int tx = threadIdx.x, ty = threadIdx.y;
#pragma unroll
    for (int i = 0; i < 4; i++) {
        int n = n0 + ty + i * 8;
        tf[ty + i * 8][tx] = g_vf[((size_t)bh * NN + n) * HDIM + d0 + tx];
    }
    __syncthreads();
#pragma unroll
    for (int i = 0; i < 4; i++) {
        int d = d0 + ty + i * 8;
        g_vtf[((size_t)bh * HDIM + d) * NN + n0 + tx] = tf[tx][ty + i * 8];
    }
}

// ============================ score: persistent-Q n-loop kernel (fp16 1-MMA) ============================
// grid (5, 192). Q tile (f16) resident; K tiles (f16) stream through a 3-stage ring.
__global__ __launch_bounds__(256, 3) void score_mma() {
    extern __shared__ char smem[];
    u32 sb = smem_u32(smem);
    const u32 A_F = 0, RING = 16384;   // K stage: 8192
    const int m0 = blockIdx.x * 128, bhi = blockIdx.y;
    const int tid = threadIdx.x, lane = tid & 31, wid = tid >> 5;
    const int wm = wid >> 1, wn = wid & 1;
    const int wrow = wm * 32, wcol = wn * 32;

    const __half* Qf = g_qf + ((size_t)bhi * NN + m0) * HDIM;
    const __half* Kf = g_kf + (size_t)bhi * NN * HDIM;

#pragma unroll
    for (int i = tid; i < 128 * 8; i += 256) {
        int r = i >> 3, cc = i & 7, kt = cc >> 2, c = cc & 3;
        u32 doff = (u32)(kt * 8192 + r * 64 + ((c ^ ((r >> 1) & 3)) << 4));
        cp16(sb + A_F + doff, Qf + (size_t)r * HDIM + kt * 32 + c * 8);
    }
    cp_commit();

    auto issueB = [&](int nt) {
        const u32 st = sb + RING + (u32)(nt % 3) * 8192;
#pragma unroll
        for (int i = tid; i < 64 * 8; i += 256) {
            int r = i >> 3, cc = i & 7, kt = cc >> 2, c = cc & 3;
            u32 doff = (u32)(kt * 4096 + r * 64 + ((c ^ ((r >> 1) & 3)) << 4));
            cp16(st + doff, Kf + (size_t)(nt * 64 + r) * HDIM + kt * 32 + c * 8);
        }
        cp_commit();
    };
    issueB(0); issueB(1);

    __half* outb = g_attnf + (size_t)bhi * NN * NN;
    for (int nt = 0; nt < 9; nt++) {
        if (nt < 8) cp_wait<1>();
        else        cp_wait<0>();
        __syncthreads();
        if (nt + 2 < 9) issueB(nt + 2);
        const u32 st = sb + RING + (u32)(nt % 3) * 8192;

        float acc[2][4][4];
#pragma unroll
        for (int i = 0; i < 2; i++)
#pragma unroll
            for (int j = 0; j < 4; j++)
#pragma unroll
                for (int k = 0; k < 4; k++) acc[i][j][k] = 0.f;

#pragma unroll
        for (int kt = 0; kt < 2; kt++)
#pragma unroll
            for (int ks = 0; ks < 2; ks++) {
                u32 bf[4][2];
                {
                    const int kc = ks * 2 + ((lane >> 3) & 1);
                    const int rb = wcol + ((lane >> 4) << 3) + (lane & 7);
#pragma unroll
                    for (int ni = 0; ni < 4; ni += 2) {
                        int r = rb + ni * 8;
                        u32 swz = (u32)(kt * 4096 + r * 64 + ((kc ^ ((r >> 1) & 3)) << 4));
                        ldm_x4(st + swz, bf[ni][0], bf[ni][1], bf[ni + 1][0], bf[ni + 1][1]);
                    }
                }
                const int kcA = ks * 2 + (lane >> 4);
#pragma unroll
                for (int mi = 0; mi < 2; mi++) {
                    int r = wrow + mi * 16 + (lane & 15);
                    u32 aoff = (u32)(kt * 8192 + r * 64 + ((kcA ^ ((r >> 1) & 3)) << 4));
                    u32 af[4];
                    ldm_x4(sb + A_F + aoff, af[0], af[1], af[2], af[3]);
#pragma unroll
                    for (int ni = 0; ni < 4; ni++) mma_f16(acc[mi][ni], af, bf[ni]);
                }
            }

        const int n0 = nt * 64;
#pragma unroll
        for (int mi = 0; mi < 2; mi++)
#pragma unroll
            for (int ni = 0; ni < 4; ni++) {
                int c = n0 + wn * 32 + ni * 8 + (lane & 3) * 2;
#pragma unroll
                for (int hf = 0; hf < 2; hf++) {
                    int m = m0 + wm * 32 + mi * 16 + (lane >> 2) + hf * 8;
                    if (m < NN)
                        *reinterpret_cast<__half2*>(outb + (size_t)m * NN + c) =
                            __floats2half2_rn(acc[mi][ni][hf * 2], acc[mi][ni][hf * 2 + 1]);
                }
            }
    }
}

// ============================ softmax + both mixes (f16 in, f16 out) ============================
__global__ __launch_bounds__(384) void softmax_mix_kernel(const float* __restrict__ Wl,
                                                          const float* __restrict__ bl,
                                                          const float* __restrict__ Ww,
                                                          const float* __restrict__ bw) {
    __shared__ __align__(16) float sm[HH][NN];
    __shared__ float wls[HH * HH], bls[HH], wws[HH * HH], bws[HH];
    const int bm = blockIdx.x;
    const int b = bm / NN, m = bm % NN;
    const int tid = threadIdx.x, lane = tid & 31, wid = tid >> 5;

    if (tid < HH * HH) { wls[tid] = Wl[tid]; wws[tid] = Ww[tid]; }
    if (tid < HH) { bls[tid] = bl[tid]; bws[tid] = bw[tid]; }

    // fp16 load: 8 halfs per uint4
    for (int idx = tid; idx < HH * NN / 8; idx += 384) {
        int h = idx / (NN / 8), n8 = idx - h * (NN / 8);
        uint4 v = *reinterpret_cast<const uint4*>(
            g_attnf + ((size_t)(b * HH + h) * NN + m) * NN + n8 * 8);
        const __half2* hp = reinterpret_cast<const __half2*>(&v);
#pragma unroll
        for (int j = 0; j < 4; j++) {
            float2 f = __half22float2(hp[j]);
            sm[h][n8 * 8 + j * 2] = f.x;
            sm[h][n8 * 8 + j * 2 + 1] = f.y;
        }
    }
    __syncthreads();

    for (int n = tid; n < NN; n += 384) {
        float p[HH];
#pragma unroll
        for (int h = 0; h < HH; h++) p[h] = sm[h][n];
#pragma unroll
        for (int g = 0; g < HH; g++) {
            float o = bls[g];
#pragma unroll
            for (int h = 0; h < HH; h++) o += wls[g * HH + h] * p[h];
            sm[g][n] = o;
        }
    }
    __syncthreads();

    {
        const int h = wid;
        float mx = -1e30f;
        for (int n = lane; n < NN; n += 32) mx = fmaxf(mx, sm[h][n]);
#pragma unroll
        for (int o = 16; o > 0; o >>= 1) mx = fmaxf(mx, __shfl_xor_sync(0xffffffffu, mx, o));
        float sum = 0.f;
        for (int n = lane; n < NN; n += 32) {
            float e = __expf(sm[h][n] - mx);
            sm[h][n] = e; sum += e;
        }
#pragma unroll
        for (int o = 16; o > 0; o >>= 1) sum += __shfl_xor_sync(0xffffffffu, sum, o);
        float inv = 1.f / sum;
        for (int n = lane; n < NN; n += 32) sm[h][n] *= inv;
    }
    __syncthreads();

    for (int n2 = tid; n2 < NN / 2; n2 += 384) {
        int n = n2 * 2;
        float p0[HH], p1[HH];
#pragma unroll
        for (int h = 0; h < HH; h++) { p0[h] = sm[h][n]; p1[h] = sm[h][n + 1]; }
#pragma unroll
        for (int g = 0; g < HH; g++) {
            float o0 = bws[g], o1 = bws[g];
#pragma unroll
            for (int h = 0; h < HH; h++) { o0 += wws[g * HH + h] * p0[h]; o1 += wws[g * HH + h] * p1[h]; }
            size_t idx = ((size_t)(b * HH + g) * NN + m) * NN + n;
            *reinterpret_cast<__half2*>(g_a2f + idx) = __floats2half2_rn(o0, o1);
        }
    }
}

// ============================ O = attn2 @ V per (b,h)  (fp16 1-MMA) ============================
// grid (5, 192). K = 576.
__global__ __launch_bounds__(256, 3) void av_mma() {
    extern __shared__ char smem[];
    u32 sb = smem_u32(smem);
    const int m0 = blockIdx.x * 128, bh = blockIdx.y;
    float acc[2][4][4];
#pragma unroll
    for (int i = 0; i < 2; i++)
#pragma unroll
        for (int j = 0; j < 4; j++)
#pragma unroll
            for (int k = 0; k < 4; k++) acc[i][j][k] = 0.f;
    const size_t ab = (size_t)bh * NN * NN + (size_t)m0 * NN;
    const size_t bb = (size_t)bh * HDIM * NN;
    gemm_core_f16s<128, 64, 4, 2>(g_a2f + ab, NN, g_vtf + bb, NN, NN, sb, acc);
    const int tid = threadIdx.x, lane = tid & 31, wid = tid >> 5;
    const int wm = wid >> 1, wn = wid & 1;
    const int b = bh / HH, h = bh - b * HH;
#pragma unroll
    for (int mi = 0; mi < 2; mi++)
#pragma unroll
        for (int ni = 0; ni < 4; ni++) {
            int dc = wn * 32 + ni * 8 + (lane & 3) * 2;
#pragma unroll
            for (int hf = 0; hf < 2; hf++) {
                int m = m0 + wm * 32 + mi * 16 + (lane >> 2) + hf * 8;
                if (m < NN) {
                    size_t base = ((size_t)b * NN + m) * CC + h * HDIM + dc;
                    *reinterpret_cast<__half2*>(g_o1f + base) =
                        __floats2half2_rn(acc[mi][ni][hf * 2], acc[mi][ni][hf * 2 + 1]);
                }
            }
        }
}

// ============================ out = o1 @ Wproj^T + bias (fp16 2-MMA, BN=128) ============================
// grid (6, 72)
__global__ __launch_bounds__(256, 2) void proj_mma(const float* __restrict__ bias,
                                                   float* __restrict__ out) {
    extern __shared__ char smem[];
    u32 sb = smem_u32(smem);
    const int n0 = blockIdx.x * 128, m0 = blockIdx.y * 128;
    float acc[4][4][4];
#pragma unroll
    for (int i = 0; i < 4; i++)
#pragma unroll
        for (int j = 0; j < 4; j++)
#pragma unroll
            for (int k = 0; k < 4; k++) acc[i][j][k] = 0.f;
    gemm_core_f16<128, 128, 2, 4>(g_o1f + (size_t)m0 * CC, CC,
                                  g_wphf + (size_t)n0 * CC, g_wplf + (size_t)n0 * CC, CC,
                                  CC, sb, acc);
    const int tid = threadIdx.x, lane = tid & 31, wid = tid >> 5;
    const int wm = wid >> 2, wn = wid & 3;
#pragma unroll
    for (int mi = 0; mi < 4; mi++)
#pragma unroll
        for (int ni = 0; ni < 4; ni++) {
            int c = n0 + wn * 32 + ni * 8 + (lane & 3) * 2;
            float b0 = __ldg(&bias[c]), b1 = __ldg(&bias[c + 1]);
#pragma unroll
            for (int hf = 0; hf < 2; hf++) {
                int m = m0 + wm * 64 + mi * 16 + (lane >> 2) + hf * 8;
                *reinterpret_cast<float2*>(out + (size_t)m * CC + c) =
                    make_float2(acc[mi][ni][hf * 2] + b0, acc[mi][ni][hf * 2 + 1] + b1);
            }
        }
}

// ============================ launch ============================
extern "C" void kernel_launch(void* const* d_in, const int* in_sizes, int n_in,
                              void* d_out, int out_size) {
    const float* x     = (const float*)d_in[0];
    const float* Wqkv  = (const float*)d_in[1];
    const float* Wl    = (const float*)d_in[2];
    const float* bl    = (const float*)d_in[3];
    const float* Ww    = (const float*)d_in[4];
    const float* bw    = (const float*)d_in[5];
    const float* Wproj = (const float*)d_in[6];
    const float* bproj = (const float*)d_in[7];
    float* out = (float*)d_out;

    static bool attr_done = false;
    if (!attr_done) {
        cudaFuncSetAttribute(qkv_mma,   cudaFuncAttributeMaxDynamicSharedMemorySize, QKV_SMEM);
        cudaFuncSetAttribute(score_mma, cudaFuncAttributeMaxDynamicSharedMemorySize, SCORE_SMEM);
        cudaFuncSetAttribute(av_mma,    cudaFuncAttributeMaxDynamicSharedMemorySize, AV_SMEM);
        cudaFuncSetAttribute(proj_mma,  cudaFuncAttributeMaxDynamicSharedMemorySize, PROJ_SMEM);
        attr_done = true;
    }

    __half *xf, *wqhf, *wqlf, *wphf, *wplf;
    cudaGetSymbolAddress((void**)&xf, g_xf);
    cudaGetSymbolAddress((void**)&wqhf, g_wqhf); cudaGetSymbolAddress((void**)&wqlf, g_wqlf);
    cudaGetSymbolAddress((void**)&wphf, g_wphf); cudaGetSymbolAddress((void**)&wplf, g_wplf);

    split_f16s_kernel<<<(MTOT * CC / 4 + 255) / 256, 256>>>(x, xf, MTOT * CC);
    split_f16_kernel<<<(3 * CC * CC / 4 + 255) / 256, 256>>>(Wqkv, wqhf, wqlf, 3 * CC * CC);
    split_f16_kernel<<<(CC * CC / 4 + 255) / 256, 256>>>(Wproj, wphf, wplf, CC * CC);

    qkv_mma<<<dim3(18, 72), 256, QKV_SMEM>>>();
    transpose_v<<<dim3(18, 2, BB * HH), dim3(32, 8)>>>();
    score_mma<<<dim3(5, BB * HH), 256, SCORE_SMEM>>>();
    softmax_mix_kernel<<<MTOT, 384>>>(Wl, bl, Ww, bw);
    av_mma<<<dim3(5, BB * HH), 256, AV_SMEM>>>();
    proj_mma<<<dim3(6, 72), 256, PROJ_SMEM>>>(bproj, out);
}

// round 16
// speedup vs baseline: 1.5449x; 1.1248x over previous
#include <cuda_runtime.h>
#include <cuda_bf16.h>
#include <cuda_fp16.h>

// Talking-heads attention via mma.sync tensor cores (plain sm_100 ISA).
// v14b: resubmission of v14 (infra flake; audit clean).
// Pure fp16 pipeline — ALL GEMMs single-f16 x single-f16, 1 MMA/k-step.
//   qkv : x f16 x Wqkv f16      score: q f16 x k f16
//   av  : attn2 f16 x V^T f16   proj : o1 f16 x Wproj f16
// fp32 accumulate everywhere; fp16 storage for all intermediates.

#define BB 16
#define NN 576
#define CC 768
#define HH 12
#define HDIM 64
#define MTOT (BB * NN)
#define SCALE 0.125f
#define ATT ((size_t)BB * HH * NN * NN)
#define QKE (BB * HH * NN * HDIM)

typedef unsigned int u32;

// ============================ PTX helpers ============================
__device__ __forceinline__ u32 smem_u32(const void* p) {
    u32 a;
    asm("{ .reg .u64 t; cvta.to.shared.u64 t, %1; cvt.u32.u64 %0, t; }" : "=r"(a) : "l"(p));
    return a;
}
__device__ __forceinline__ void cp16(u32 dst, const void* src) {
    asm volatile("cp.async.cg.shared.global [%0], [%1], 16;" :: "r"(dst), "l"(src));
}
__device__ __forceinline__ void cp_commit() {
    asm volatile("cp.async.commit_group;" ::: "memory");
}
template <int N>
__device__ __forceinline__ void cp_wait() {
    asm volatile("cp.async.wait_group %0;" :: "n"(N) : "memory");
}
__device__ __forceinline__ void ldm_x4(u32 a, u32& r0, u32& r1, u32& r2, u32& r3) {
    asm volatile("ldmatrix.sync.aligned.m8n8.x4.shared.b16 {%0,%1,%2,%3}, [%4];"
                 : "=r"(r0), "=r"(r1), "=r"(r2), "=r"(r3) : "r"(a));
}
__device__ __forceinline__ void mma_f16(float* d, const u32* a, const u32* b) {
    asm volatile("mma.sync.aligned.m16n8k16.row.col.f32.f16.f16.f32 "
                 "{%0,%1,%2,%3}, {%4,%5,%6,%7}, {%8,%9}, {%0,%1,%2,%3};"
                 : "+f"(d[0]), "+f"(d[1]), "+f"(d[2]), "+f"(d[3])
                 : "r"(a[0]), "r"(a[1]), "r"(a[2]), "r"(a[3]), "r"(b[0]), "r"(b[1]));
}

// ============================ scratch (16B-aligned; generous pads) ============================
__device__ __align__(16) __half g_xf[MTOT * CC];                // x f16
__device__ __align__(16) __half g_wqf[3 * CC * CC];             // Wqkv f16
__device__ __align__(16) __half g_qf[QKE + 128 * HDIM];         // q f16 (pre-scaled)
__device__ __align__(16) __half g_kf[QKE + 128 * HDIM];         // k f16
__device__ __align__(16) __half g_vf[QKE];                      // v f16
__device__ __align__(16) __half g_vtf[QKE];                     // v^T f16
__device__ __align__(16) __half g_attnf[ATT + 128 * NN];        // raw scores f16
__device__ __align__(16) __half g_a2f[ATT + 128 * NN];          // attn2 f16
__device__ __align__(16) __half g_o1f[MTOT * CC];               // o1 f16
__device__ __align__(16) __half g_wpf[CC * CC];                 // Wproj f16

// ============================ fp16 single/single GEMM core (3-stage, 1-MMA) ============================
template <int BM, int BN, int TMW, int TNW>
__device__ __forceinline__ void gemm_core_f16s(
    const __half* __restrict__ Af, int lda,
    const __half* __restrict__ Bf, int ldb,
    int K, u32 sb, float (*acc)[4][4]) {
    constexpr int MI = BM / TMW / 16;
    constexpr int NI = BN / TNW / 8;
    static_assert(NI == 4, "epilogue layout assumes NI==4");
    constexpr u32 OFF_B = BM * 64;
    constexpr u32 SS = (BM + BN) * 64;
    const int tid = threadIdx.x;
    const int lane = tid & 31, wid = tid >> 5;
    const int wrow = (wid / TNW) * (BM / TMW);
    const int wcol = (wid % TNW) * (BN / TNW);
    const int NK = K >> 5;

    auto issue = [&](int kt) {
        const u32 st = sb + (u32)(kt % 3) * SS;
        const int k0 = kt << 5;
#pragma unroll
        for (int i = tid; i < BM * 4; i += 256) {
            int r = i >> 2, c = i & 3;
            u32 doff = (u32)(r * 64 + ((c ^ ((r >> 1) & 3)) << 4));
            cp16(st + doff, Af + (size_t)r * lda + k0 + c * 8);
        }
#pragma unroll
        for (int i = tid; i < BN * 4; i += 256) {
            int r = i >> 2, c = i & 3;
            u32 doff = (u32)(r * 64 + ((c ^ ((r >> 1) & 3)) << 4));
            cp16(st + OFF_B + doff, Bf + (size_t)r * ldb + k0 + c * 8);
        }
        cp_commit();
    };

    issue(0);
    if (NK > 1) issue(1);
    for (int kt = 0; kt < NK; kt++) {
        if (kt + 1 < NK) cp_wait<1>();
        else             cp_wait<0>();
        __syncthreads();
        if (kt + 2 < NK) issue(kt + 2);
        const u32 st = sb + (u32)(kt % 3) * SS;
#pragma unroll
        for (int ks = 0; ks < 2; ks++) {
            u32 bf[NI][2];
            {
                const int kc = ks * 2 + ((lane >> 3) & 1);
                const int rb = wcol + ((lane >> 4) << 3) + (lane & 7);
#pragma unroll
                for (int ni = 0; ni < NI; ni += 2) {
                    int r = rb + ni * 8;
                    u32 swz = (u32)(r * 64 + ((kc ^ ((r >> 1) & 3)) << 4));
                    ldm_x4(st + OFF_B + swz, bf[ni][0], bf[ni][1], bf[ni + 1][0], bf[ni + 1][1]);
                }
            }
            const int kcA = ks * 2 + (lane >> 4);
#pragma unroll
            for (int mi = 0; mi < MI; mi++) {
                int r = wrow + mi * 16 + (lane & 15);
                u32 a = st + (u32)(r * 64 + ((kcA ^ ((r >> 1) & 3)) << 4));
                u32 af[4];
                ldm_x4(a, af[0], af[1], af[2], af[3]);
#pragma unroll
                for (int ni = 0; ni < NI; ni++) mma_f16(acc[mi][ni], af, bf[ni]);
            }
        }
    }
}

#define QKV_SMEM   49152   // 3 x 16384 (A 8K + B 8K)
#define SCORE_SMEM 40960   // A 16K resident + 3 x 8192
#define AV_SMEM    36864   // 3 x 12288 (A 8K + B 4K)
#define PROJ_SMEM  49152   // 3 x 16384

// ============================ fp32 -> fp16 single ============================
__global__ __launch_bounds__(256) void split_f16s_kernel(const float* __restrict__ in,
                                                         __half* __restrict__ o, int n) {
    int i = (blockIdx.x * 256 + threadIdx.x) * 4;
    if (i >= n) return;
    float4 v = *reinterpret_cast<const float4*>(in + i);
    __half2 a = __floats2half2_rn(v.x, v.y);
    __half2 b = __floats2half2_rn(v.z, v.w);
    *reinterpret_cast<uint2*>(o + i) = make_uint2(*(u32*)&a, *(u32*)&b);
}

// ============================ QKV GEMM + scatter (f16 1-MMA, BN=128) ============================
// grid (18, 72)
__global__ __launch_bounds__(256, 2) void qkv_mma() {
    extern __shared__ char smem[];
    u32 sb = smem_u32(smem);
    const int n0 = blockIdx.x * 128, m0 = blockIdx.y * 128;
    float acc[4][4][4];
#pragma unroll
    for (int i = 0; i < 4; i++)
#pragma unroll
        for (int j = 0; j < 4; j++)
#pragma unroll
            for (int k = 0; k < 4; k++) acc[i][j][k] = 0.f;
    gemm_core_f16s<128, 128, 2, 4>(g_xf + (size_t)m0 * CC, CC,
                                   g_wqf + (size_t)n0 * CC, CC, CC, sb, acc);
    const int tid = threadIdx.x, lane = tid & 31, wid = tid >> 5;
    const int wm = wid >> 2, wn = wid & 3;
#pragma unroll
    for (int mi = 0; mi < 4; mi++)
#pragma unroll
        for (int ni = 0; ni < 4; ni++) {
            int c = n0 + wn * 32 + ni * 8 + (lane & 3) * 2;
            int t = c / CC, rc = c - t * CC, h = rc >> 6, d0 = rc & 63;
            float sc = (t == 0) ? SCALE : 1.f;
            __half* dst = (t == 0) ? g_qf : (t == 1) ? g_kf : g_vf;
#pragma unroll
            for (int hf = 0; hf < 2; hf++) {
                int m = m0 + wm * 64 + mi * 16 + (lane >> 2) + hf * 8;
                int b = m / NN, ntok = m - b * NN;
                size_t base = ((size_t)(b * HH + h) * NN + ntok) * HDIM + d0;
                *reinterpret_cast<__half2*>(dst + base) =
                    __floats2half2_rn(acc[mi][ni][hf * 2] * sc, acc[mi][ni][hf * 2 + 1] * sc);
            }
        }
}

// ============================ transpose V -> vT[d][n] (f16) ============================
__global__ __launch_bounds__(256) void transpose_v() {
    __shared__ __half tf[32][34];
    int n0 = blockIdx.x * 32, d0 = blockIdx.y * 32, bh = blockIdx.z;
    int tx = threadIdx.x, ty = threadIdx.y;
#pragma unroll
    for (int i = 0; i < 4; i++) {
        int n = n0 + ty + i * 8;
        tf[ty + i * 8][tx] = g_vf[((size_t)bh * NN + n) * HDIM + d0 + tx];
    }
    __syncthreads();
#pragma unroll
    for (int i = 0; i < 4; i++) {
        int d = d0 + ty + i * 8;
        g_vtf[((size_t)bh * HDIM + d) * NN + n0 + tx] = tf[tx][ty + i * 8];
    }
}

// ============================ score: persistent-Q n-loop kernel (f16 1-MMA) ============================
// grid (5, 192). Q tile resident; K tiles stream through a 3-stage ring.
__global__ __launch_bounds__(256, 3) void score_mma() {
    extern __shared__ char smem[];
    u32 sb = smem_u32(smem);
    const u32 A_F = 0, RING = 16384;
    const int m0 = blockIdx.x * 128, bhi = blockIdx.y;
    const int tid = threadIdx.x, lane = tid & 31, wid = tid >> 5;
    const int wm = wid >> 1, wn = wid & 1;
    const int wrow = wm * 32, wcol = wn * 32;

    const __half* Qf = g_qf + ((size_t)bhi * NN + m0) * HDIM;
    const __half* Kf = g_kf + (size_t)bhi * NN * HDIM;

#pragma unroll
    for (int i = tid; i < 128 * 8; i += 256) {
        int r = i >> 3, cc = i & 7, kt = cc >> 2, c = cc & 3;
        u32 doff = (u32)(kt * 8192 + r * 64 + ((c ^ ((r >> 1) & 3)) << 4));
        cp16(sb + A_F + doff, Qf + (size_t)r * HDIM + kt * 32 + c * 8);
    }
    cp_commit();

    auto issueB = [&](int nt) {
        const u32 st = sb + RING + (u32)(nt % 3) * 8192;
#pragma unroll
        for (int i = tid; i < 64 * 8; i += 256) {
            int r = i >> 3, cc = i & 7, kt = cc >> 2, c = cc & 3;
            u32 doff = (u32)(kt * 4096 + r * 64 + ((c ^ ((r >> 1) & 3)) << 4));
            cp16(st + doff, Kf + (size_t)(nt * 64 + r) * HDIM + kt * 32 + c * 8);
        }
        cp_commit();
    };
    issueB(0); issueB(1);

    __half* outb = g_attnf + (size_t)bhi * NN * NN;
    for (int nt = 0; nt < 9; nt++) {
        if (nt < 8) cp_wait<1>();
        else        cp_wait<0>();
        __syncthreads();
        if (nt + 2 < 9) issueB(nt + 2);
        const u32 st = sb + RING + (u32)(nt % 3) * 8192;

        float acc[2][4][4];
#pragma unroll
        for (int i = 0; i < 2; i++)
#pragma unroll
            for (int j = 0; j < 4; j++)
#pragma unroll
                for (int k = 0; k < 4; k++) acc[i][j][k] = 0.f;

#pragma unroll
        for (int kt = 0; kt < 2; kt++)
#pragma unroll
            for (int ks = 0; ks < 2; ks++) {
                u32 bf[4][2];
                {
                    const int kc = ks * 2 + ((lane >> 3) & 1);
                    const int rb = wcol + ((lane >> 4) << 3) + (lane & 7);
#pragma unroll
                    for (int ni = 0; ni < 4; ni += 2) {
                        int r = rb + ni * 8;
                        u32 swz = (u32)(kt * 4096 + r * 64 + ((kc ^ ((r >> 1) & 3)) << 4));
                        ldm_x4(st + swz, bf[ni][0], bf[ni][1], bf[ni + 1][0], bf[ni + 1][1]);
                    }
                }
                const int kcA = ks * 2 + (lane >> 4);
#pragma unroll
                for (int mi = 0; mi < 2; mi++) {
                    int r = wrow + mi * 16 + (lane & 15);
                    u32 aoff = (u32)(kt * 8192 + r * 64 + ((kcA ^ ((r >> 1) & 3)) << 4));
                    u32 af[4];
                    ldm_x4(sb + A_F + aoff, af[0], af[1], af[2], af[3]);
#pragma unroll
                    for (int ni = 0; ni < 4; ni++) mma_f16(acc[mi][ni], af, bf[ni]);
                }
            }

        const int n0 = nt * 64;
#pragma unroll
        for (int mi = 0; mi < 2; mi++)
#pragma unroll
            for (int ni = 0; ni < 4; ni++) {
                int c = n0 + wn * 32 + ni * 8 + (lane & 3) * 2;
#pragma unroll
                for (int hf = 0; hf < 2; hf++) {
                    int m = m0 + wm * 32 + mi * 16 + (lane >> 2) + hf * 8;
                    if (m < NN)
                        *reinterpret_cast<__half2*>(outb + (size_t)m * NN + c) =
                            __floats2half2_rn(acc[mi][ni][hf * 2], acc[mi][ni][hf * 2 + 1]);
                }
            }
    }
}

// ============================ softmax + both mixes (f16 in, f16 out) ============================
__global__ __launch_bounds__(384) void softmax_mix_kernel(const float* __restrict__ Wl,
                                                          const float* __restrict__ bl,
                                                          const float* __restrict__ Ww,
                                                          const float* __restrict__ bw) {
    __shared__ __align__(16) float sm[HH][NN];
    __shared__ float wls[HH * HH], bls[HH], wws[HH * HH], bws[HH];
    const int bm = blockIdx.x;
    const int b = bm / NN, m = bm % NN;
    const int tid = threadIdx.x, lane = tid & 31, wid = tid >> 5;

    if (tid < HH * HH) { wls[tid] = Wl[tid]; wws[tid] = Ww[tid]; }
    if (tid < HH) { bls[tid] = bl[tid]; bws[tid] = bw[tid]; }

    for (int idx = tid; idx < HH * NN / 8; idx += 384) {
        int h = idx / (NN / 8), n8 = idx - h * (NN / 8);
        uint4 v = *reinterpret_cast<const uint4*>(
            g_attnf + ((size_t)(b * HH + h) * NN + m) * NN + n8 * 8);
        const __half2* hp = reinterpret_cast<const __half2*>(&v);
#pragma unroll
        for (int j = 0; j < 4; j++) {
            float2 f = __half22float2(hp[j]);
            sm[h][n8 * 8 + j * 2] = f.x;
            sm[h][n8 * 8 + j * 2 + 1] = f.y;
        }
    }
    __syncthreads();

    for (int n = tid; n < NN; n += 384) {
        float p[HH];
#pragma unroll
        for (int h = 0; h < HH; h++) p[h] = sm[h][n];
#pragma unroll
        for (int g = 0; g < HH; g++) {
            float o = bls[g];
#pragma unroll
            for (int h = 0; h < HH; h++) o += wls[g * HH + h] * p[h];
            sm[g][n] = o;
        }
    }
    __syncthreads();

    {
        const int h = wid;
        float mx = -1e30f;
        for (int n = lane; n < NN; n += 32) mx = fmaxf(mx, sm[h][n]);
#pragma unroll
        for (int o = 16; o > 0; o >>= 1) mx = fmaxf(mx, __shfl_xor_sync(0xffffffffu, mx, o));
        float sum = 0.f;
        for (int n = lane; n < NN; n += 32) {
            float e = __expf(sm[h][n] - mx);
            sm[h][n] = e; sum += e;
        }
#pragma unroll
        for (int o = 16; o > 0; o >>= 1) sum += __shfl_xor_sync(0xffffffffu, sum, o);
        float inv = 1.f / sum;
        for (int n = lane; n < NN; n += 32) sm[h][n] *= inv;
    }
    __syncthreads();

    for (int n2 = tid; n2 < NN / 2; n2 += 384) {
        int n = n2 * 2;
        float p0[HH], p1[HH];
#pragma unroll
        for (int h = 0; h < HH; h++) { p0[h] = sm[h][n]; p1[h] = sm[h][n + 1]; }
#pragma unroll
        for (int g = 0; g < HH; g++) {
            float o0 = bws[g], o1 = bws[g];
#pragma unroll
            for (int h = 0; h < HH; h++) { o0 += wws[g * HH + h] * p0[h]; o1 += wws[g * HH + h] * p1[h]; }
            size_t idx = ((size_t)(b * HH + g) * NN + m) * NN + n;
            *reinterpret_cast<__half2*>(g_a2f + idx) = __floats2half2_rn(o0, o1);
        }
    }
}

// ============================ O = attn2 @ V per (b,h)  (f16 1-MMA) ============================
// grid (5, 192). K = 576.
__global__ __launch_bounds__(256, 3) void av_mma() {
    extern __shared__ char smem[];
    u32 sb = smem_u32(smem);
    const int m0 = blockIdx.x * 128, bh = blockIdx.y;
    float acc[2][4][4];
#pragma unroll
    for (int i = 0; i < 2; i++)
#pragma unroll
        for (int j = 0; j < 4; j++)
#pragma unroll
            for (int k = 0; k < 4; k++) acc[i][j][k] = 0.f;
    const size_t ab = (size_t)bh * NN * NN + (size_t)m0 * NN;
    const size_t bb = (size_t)bh * HDIM * NN;
    gemm_core_f16s<128, 64, 4, 2>(g_a2f + ab, NN, g_vtf + bb, NN, NN, sb, acc);
    const int tid = threadIdx.x, lane = tid & 31, wid = tid >> 5;
    const int wm = wid >> 1, wn = wid & 1;
    const int b = bh / HH, h = bh - b * HH;
#pragma unroll
    for (int mi = 0; mi < 2; mi++)
#pragma unroll
        for (int ni = 0; ni < 4; ni++) {
            int dc = wn * 32 + ni * 8 + (lane & 3) * 2;
#pragma unroll
            for (int hf = 0; hf < 2; hf++) {
                int m = m0 + wm * 32 + mi * 16 + (lane >> 2) + hf * 8;
                if (m < NN) {
                    size_t base = ((size_t)b * NN + m) * CC + h * HDIM + dc;
                    *reinterpret_cast<__half2*>(g_o1f + base) =
                        __floats2half2_rn(acc[mi][ni][hf * 2], acc[mi][ni][hf * 2 + 1]);
                }
            }
        }
}

// ============================ out = o1 @ Wproj^T + bias (f16 1-MMA, BN=128) ============================
// grid (6, 72)
__global__ __launch_bounds__(256, 2) void proj_mma(const float* __restrict__ bias,
                                                   float* __restrict__ out) {
    extern __shared__ char smem[];
    u32 sb = smem_u32(smem);
    const int n0 = blockIdx.x * 128, m0 = blockIdx.y * 128;
    float acc[4][4][4];
#pragma unroll
    for (int i = 0; i < 4; i++)
#pragma unroll
        for (int j = 0; j < 4; j++)
#pragma unroll
            for (int k = 0; k < 4; k++) acc[i][j][k] = 0.f;
    gemm_core_f16s<128, 128, 2, 4>(g_o1f + (size_t)m0 * CC, CC,
                                   g_wpf + (size_t)n0 * CC, CC, CC, sb, acc);
    const int tid = threadIdx.x, lane = tid & 31, wid = tid >> 5;
    const int wm = wid >> 2, wn = wid & 3;
#pragma unroll
    for (int mi = 0; mi < 4; mi++)
#pragma unroll
        for (int ni = 0; ni < 4; ni++) {
            int c = n0 + wn * 32 + ni * 8 + (lane & 3) * 2;
            float b0 = __ldg(&bias[c]), b1 = __ldg(&bias[c + 1]);
#pragma unroll
            for (int hf = 0; hf < 2; hf++) {
                int m = m0 + wm * 64 + mi * 16 + (lane >> 2) + hf * 8;
                *reinterpret_cast<float2*>(out + (size_t)m * CC + c) =
                    make_float2(acc[mi][ni][hf * 2] + b0, acc[mi][ni][hf * 2 + 1] + b1);
            }
        }
}

// ============================ launch ============================
extern "C" void kernel_launch(void* const* d_in, const int* in_sizes, int n_in,
                              void* d_out, int out_size) {
    const float* x     = (const float*)d_in[0];
    const float* Wqkv  = (const float*)d_in[1];
    const float* Wl    = (const float*)d_in[2];
    const float* bl    = (const float*)d_in[3];
    const float* Ww    = (const float*)d_in[4];
    const float* bw    = (const float*)d_in[5];
    const float* Wproj = (const float*)d_in[6];
    const float* bproj = (const float*)d_in[7];
    float* out = (float*)d_out;

    static bool attr_done = false;
    if (!attr_done) {
        cudaFuncSetAttribute(qkv_mma,   cudaFuncAttributeMaxDynamicSharedMemorySize, QKV_SMEM);
        cudaFuncSetAttribute(score_mma, cudaFuncAttributeMaxDynamicSharedMemorySize, SCORE_SMEM);
        cudaFuncSetAttribute(av_mma,    cudaFuncAttributeMaxDynamicSharedMemorySize, AV_SMEM);
        cudaFuncSetAttribute(proj_mma,  cudaFuncAttributeMaxDynamicSharedMemorySize, PROJ_SMEM);
        attr_done = true;
    }

    __half *xf, *wqf, *wpf;
    cudaGetSymbolAddress((void**)&xf, g_xf);
    cudaGetSymbolAddress((void**)&wqf, g_wqf);
    cudaGetSymbolAddress((void**)&wpf, g_wpf);

    split_f16s_kernel<<<(MTOT * CC / 4 + 255) / 256, 256>>>(x, xf, MTOT * CC);
    split_f16s_kernel<<<(3 * CC * CC / 4 + 255) / 256, 256>>>(Wqkv, wqf, 3 * CC * CC);
    split_f16s_kernel<<<(CC * CC / 4 + 255) / 256, 256>>>(Wproj, wpf, CC * CC);

    qkv_mma<<<dim3(18, 72), 256, QKV_SMEM>>>();
    transpose_v<<<dim3(18, 2, BB * HH), dim3(32, 8)>>>();
    score_mma<<<dim3(5, BB * HH), 256, SCORE_SMEM>>>();
    softmax_mix_kernel<<<MTOT, 384>>>(Wl, bl, Ww, bw);
    av_mma<<<dim3(5, BB * HH), 256, AV_SMEM>>>();
    proj_mma<<<dim3(6, 72), 256, PROJ_SMEM>>>(bproj, out);
}

// round 17
// speedup vs baseline: 1.5946x; 1.0322x over previous
#include <cuda_runtime.h>
#include <cuda_bf16.h>
#include <cuda_fp16.h>

// Talking-heads attention via mma.sync tensor cores (plain sm_100 ISA).
// v15: pure fp16 pipeline; BK=64 staging (128B swizzled rows) for qkv/av/proj
//      halves barrier/commit count per CTA. Numerics identical to v14.

#define BB 16
#define NN 576
#define CC 768
#define HH 12
#define HDIM 64
#define MTOT (BB * NN)
#define SCALE 0.125f
#define ATT ((size_t)BB * HH * NN * NN)
#define QKE (BB * HH * NN * HDIM)

typedef unsigned int u32;

// ============================ PTX helpers ============================
__device__ __forceinline__ u32 smem_u32(const void* p) {
    u32 a;
    asm("{ .reg .u64 t; cvta.to.shared.u64 t, %1; cvt.u32.u64 %0, t; }" : "=r"(a) : "l"(p));
    return a;
}
__device__ __forceinline__ void cp16(u32 dst, const void* src) {
    asm volatile("cp.async.cg.shared.global [%0], [%1], 16;" :: "r"(dst), "l"(src));
}
__device__ __forceinline__ void cp_commit() {
    asm volatile("cp.async.commit_group;" ::: "memory");
}
template <int N>
__device__ __forceinline__ void cp_wait() {
    asm volatile("cp.async.wait_group %0;" :: "n"(N) : "memory");
}
__device__ __forceinline__ void ldm_x4(u32 a, u32& r0, u32& r1, u32& r2, u32& r3) {
    asm volatile("ldmatrix.sync.aligned.m8n8.x4.shared.b16 {%0,%1,%2,%3}, [%4];"
                 : "=r"(r0), "=r"(r1), "=r"(r2), "=r"(r3) : "r"(a));
}
__device__ __forceinline__ void mma_f16(float* d, const u32* a, const u32* b) {
    asm volatile("mma.sync.aligned.m16n8k16.row.col.f32.f16.f16.f32 "
                 "{%0,%1,%2,%3}, {%4,%5,%6,%7}, {%8,%9}, {%0,%1,%2,%3};"
                 : "+f"(d[0]), "+f"(d[1]), "+f"(d[2]), "+f"(d[3])
                 : "r"(a[0]), "r"(a[1]), "r"(a[2]), "r"(a[3]), "r"(b[0]), "r"(b[1]));
}

// ============================ scratch (16B-aligned; generous pads) ============================
__device__ __align__(16) __half g_xf[MTOT * CC];                // x f16
__device__ __align__(16) __half g_wqf[3 * CC * CC];             // Wqkv f16
__device__ __align__(16) __half g_qf[QKE + 128 * HDIM];         // q f16 (pre-scaled)
__device__ __align__(16) __half g_kf[QKE + 128 * HDIM];         // k f16
__device__ __align__(16) __half g_vf[QKE];                      // v f16
__device__ __align__(16) __half g_vtf[QKE];                     // v^T f16
__device__ __align__(16) __half g_attnf[ATT + 128 * NN];        // raw scores f16
__device__ __align__(16) __half g_a2f[ATT + 128 * NN];          // attn2 f16
__device__ __align__(16) __half g_o1f[MTOT * CC];               // o1 f16
__device__ __align__(16) __half g_wpf[CC * CC];                 // Wproj f16

// ============================ fp16 single/single GEMM core, BK=64 (3-stage, 1-MMA) ============
// 128B rows (64 halfs), swizzle chunk c^(r&7): ldmatrix phases conflict-free.
template <int BM, int BN, int TMW, int TNW>
__device__ __forceinline__ void gemm_core_f16s64(
    const __half* __restrict__ Af, int lda,
    const __half* __restrict__ Bf, int ldb,
    int K, u32 sb, float (*acc)[4][4]) {
    constexpr int MI = BM / TMW / 16;
    constexpr int NI = BN / TNW / 8;
    static_assert(NI == 4, "epilogue layout assumes NI==4");
    constexpr u32 OFF_B = BM * 128;
    constexpr u32 SS = (BM + BN) * 128;
    const int tid = threadIdx.x;
    const int lane = tid & 31, wid = tid >> 5;
    const int wrow = (wid / TNW) * (BM / TMW);
    const int wcol = (wid % TNW) * (BN / TNW);
    const int NK = K >> 6;

    auto issue = [&](int kt) {
        const u32 st = sb + (u32)(kt % 3) * SS;
        const int k0 = kt << 6;
#pragma unroll
        for (int i = tid; i < BM * 8; i += 256) {
            int r = i >> 3, c = i & 7;
            u32 doff = (u32)(r * 128 + ((c ^ (r & 7)) << 4));
            cp16(st + doff, Af + (size_t)r * lda + k0 + c * 8);
        }
#pragma unroll
        for (int i = tid; i < BN * 8; i += 256) {
            int r = i >> 3, c = i & 7;
            u32 doff = (u32)(r * 128 + ((c ^ (r & 7)) << 4));
            cp16(st + OFF_B + doff, Bf + (size_t)r * ldb + k0 + c * 8);
        }
        cp_commit();
    };

    issue(0);
    if (NK > 1) issue(1);
    for (int kt = 0; kt < NK; kt++) {
        if (kt + 1 < NK) cp_wait<1>();
        else             cp_wait<0>();
        __syncthreads();
        if (kt + 2 < NK) issue(kt + 2);
        const u32 st = sb + (u32)(kt % 3) * SS;
#pragma unroll
        for (int ks = 0; ks < 4; ks++) {
            u32 bf[NI][2];
            {
                const int kc = ks * 2 + ((lane >> 3) & 1);
                const int rb = wcol + ((lane >> 4) << 3) + (lane & 7);
#pragma unroll
                for (int ni = 0; ni < NI; ni += 2) {
                    int r = rb + ni * 8;
                    u32 swz = (u32)(r * 128 + ((kc ^ (r & 7)) << 4));
                    ldm_x4(st + OFF_B + swz, bf[ni][0], bf[ni][1], bf[ni + 1][0], bf[ni + 1][1]);
                }
            }
            const int kcA = ks * 2 + (lane >> 4);
#pragma unroll
            for (int mi = 0; mi < MI; mi++) {
                int r = wrow + mi * 16 + (lane & 15);
                u32 a = st + (u32)(r * 128 + ((kcA ^ (r & 7)) << 4));
                u32 af[4];
                ldm_x4(a, af[0], af[1], af[2], af[3]);
#pragma unroll
                for (int ni = 0; ni < NI; ni++) mma_f16(acc[mi][ni], af, bf[ni]);
            }
        }
    }
}

#define QKV_SMEM   98304   // 3 x 32768 (A 16K + B 16K), BK=64
#define SCORE_SMEM 40960   // A 16K resident + 3 x 8192 (BK=32 path)
#define AV_SMEM    73728   // 3 x 24576 (A 16K + B 8K), BK=64
#define PROJ_SMEM  98304   // 3 x 32768

// ============================ combined fp32 -> fp16 conversion ============================
// ranges: [0, NX) -> x, [NX, NX+NWQ) -> Wqkv, [NX+NWQ, total) -> Wproj  (units: float4)
#define NXQ   (MTOT * CC / 4)
#define NWQQ  (3 * CC * CC / 4)
#define NWPQ  (CC * CC / 4)
__global__ __launch_bounds__(256) void split_all_kernel(const float* __restrict__ x,
                                                        const float* __restrict__ wq,
                                                        const float* __restrict__ wp,
                                                        __half* __restrict__ xf,
                                                        __half* __restrict__ wqf,
                                                        __half* __restrict__ wpf) {
    int q = blockIdx.x * 256 + threadIdx.x;
    const float* src;
    __half* dst;
    int base;
    if (q < NXQ)                  { src = x;  dst = xf;  base = 0; }
    else if (q < NXQ + NWQQ)      { src = wq; dst = wqf; base = NXQ; }
    else if (q < NXQ + NWQQ + NWPQ) { src = wp; dst = wpf; base = NXQ + NWQQ; }
    else return;
    int i = (q - base) * 4;
    float4 v = *reinterpret_cast<const float4*>(src + i);
    __half2 a = __floats2half2_rn(v.x, v.y);
    __half2 b = __floats2half2_rn(v.z, v.w);
    *reinterpret_cast<uint2*>(dst + i) = make_uint2(*(u32*)&a, *(u32*)&b);
}

// ============================ QKV GEMM + scatter (f16 1-MMA, BN=128, BK=64) ============================
// grid (18, 72)
__global__ __launch_bounds__(256, 2) void qkv_mma() {
    extern __shared__ char smem[];
    u32 sb = smem_u32(smem);
    const int n0 = blockIdx.x * 128, m0 = blockIdx.y * 128;
    float acc[4][4][4];
#pragma unroll
    for (int i = 0; i < 4; i++)
#pragma unroll
        for (int j = 0; j < 4; j++)
#pragma unroll
            for (int k = 0; k < 4; k++) acc[i][j][k] = 0.f;
    gemm_core_f16s64<128, 128, 2, 4>(g_xf + (size_t)m0 * CC, CC,
                                     g_wqf + (size_t)n0 * CC, CC, CC, sb, acc);
    const int tid = threadIdx.x, lane = tid & 31, wid = tid >> 5;
    const int wm = wid >> 2, wn = wid & 3;
#pragma unroll
    for (int mi = 0; mi < 4; mi++)
#pragma unroll
        for (int ni = 0; ni < 4; ni++) {
            int c = n0 + wn * 32 + ni * 8 + (lane & 3) * 2;
            int t = c / CC, rc = c - t * CC, h = rc >> 6, d0 = rc & 63;
            float sc = (t == 0) ? SCALE : 1.f;
            __half* dst = (t == 0) ? g_qf : (t == 1) ? g_kf : g_vf;
#pragma unroll
            for (int hf = 0; hf < 2; hf++) {
                int m = m0 + wm * 64 + mi * 16 + (lane >> 2) + hf * 8;
                int b = m / NN, ntok = m - b * NN;
                size_t base = ((size_t)(b * HH + h) * NN + ntok) * HDIM + d0;
                *reinterpret_cast<__half2*>(dst + base) =
                    __floats2half2_rn(acc[mi][ni][hf * 2] * sc, acc[mi][ni][hf * 2 + 1] * sc);
            }
        }
}

// ============================ transpose V -> vT[d][n] (f16) ============================
__global__ __launch_bounds__(256) void transpose_v() {
    __shared__ __half tf[32][34];
    int n0 = blockIdx.x * 32, d0 = blockIdx.y * 32, bh = blockIdx.z;
    int tx = threadIdx.x, ty = threadIdx.y;
#pragma unroll
    for (int i = 0; i < 4; i++) {
        int n = n0 + ty + i * 8;
        tf[ty + i * 8][tx] = g_vf[((size_t)bh * NN + n) * HDIM + d0 + tx];
    }
    __syncthreads();
#pragma unroll
    for (int i = 0; i < 4; i++) {
        int d = d0 + ty + i * 8;
        g_vtf[((size_t)bh * HDIM + d) * NN + n0 + tx] = tf[tx][ty + i * 8];
    }
}

// ============================ score: persistent-Q n-loop kernel (f16 1-MMA, BK=32 path) ============
// grid (5, 192). Q tile resident; K tiles stream through a 3-stage ring.
__global__ __launch_bounds__(256, 3) void score_mma() {
    extern __shared__ char smem[];
    u32 sb = smem_u32(smem);
    const u32 A_F = 0, RING = 16384;
    const int m0 = blockIdx.x * 128, bhi = blockIdx.y;
    const int tid = threadIdx.x, lane = tid & 31, wid = tid >> 5;
    const int wm = wid >> 1, wn = wid & 1;
    const int wrow = wm * 32, wcol = wn * 32;

    const __half* Qf = g_qf + ((size_t)bhi * NN + m0) * HDIM;
    const __half* Kf = g_kf + (size_t)bhi * NN * HDIM;

#pragma unroll
    for (int i = tid; i < 128 * 8; i += 256) {
        int r = i >> 3, cc = i & 7, kt = cc >> 2, c = cc & 3;
        u32 doff = (u32)(kt * 8192 + r * 64 + ((c ^ ((r >> 1) & 3)) << 4));
        cp16(sb + A_F + doff, Qf + (size_t)r * HDIM + kt * 32 + c * 8);
    }
    cp_commit();

    auto issueB = [&](int nt) {
        const u32 st = sb + RING + (u32)(nt % 3) * 8192;
#pragma unroll
        for (int i = tid; i < 64 * 8; i += 256) {
            int r = i >> 3, cc = i & 7, kt = cc >> 2, c = cc & 3;
            u32 doff = (u32)(kt * 4096 + r * 64 + ((c ^ ((r >> 1) & 3)) << 4));
            cp16(st + doff, Kf + (size_t)(nt * 64 + r) * HDIM + kt * 32 + c * 8);
        }
        cp_commit();
    };
    issueB(0); issueB(1);

    __half* outb = g_attnf + (size_t)bhi * NN * NN;
    for (int nt = 0; nt < 9; nt++) {
        if (nt < 8) cp_wait<1>();
        else        cp_wait<0>();
        __syncthreads();
        if (nt + 2 < 9) issueB(nt + 2);
        const u32 st = sb + RING + (u32)(nt % 3) * 8192;

        float acc[2][4][4];
#pragma unroll
        for (int i = 0; i < 2; i++)
#pragma unroll
            for (int j = 0; j < 4; j++)
#pragma unroll
                for (int k = 0; k < 4; k++) acc[i][j][k] = 0.f;

#pragma unroll
        for (int kt = 0; kt < 2; kt++)
#pragma unroll
            for (int ks = 0; ks < 2; ks++) {
                u32 bf[4][2];
                {
                    const int kc = ks * 2 + ((lane >> 3) & 1);
                    const int rb = wcol + ((lane >> 4) << 3) + (lane & 7);
#pragma unroll
                    for (int ni = 0; ni < 4; ni += 2) {
                        int r = rb + ni * 8;
                        u32 swz = (u32)(kt * 4096 + r * 64 + ((kc ^ ((r >> 1) & 3)) << 4));
                        ldm_x4(st + swz, bf[ni][0], bf[ni][1], bf[ni + 1][0], bf[ni + 1][1]);
                    }
                }
                const int kcA = ks * 2 + (lane >> 4);
#pragma unroll
                for (int mi = 0; mi < 2; mi++) {
                    int r = wrow + mi * 16 + (lane & 15);
                    u32 aoff = (u32)(kt * 8192 + r * 64 + ((kcA ^ ((r >> 1) & 3)) << 4));
                    u32 af[4];
                    ldm_x4(sb + A_F + aoff, af[0], af[1], af[2], af[3]);
#pragma unroll
                    for (int ni = 0; ni < 4; ni++) mma_f16(acc[mi][ni], af, bf[ni]);
                }
            }

        const int n0 = nt * 64;
#pragma unroll
        for (int mi = 0; mi < 2; mi++)
#pragma unroll
            for (int ni = 0; ni < 4; ni++) {
                int c = n0 + wn * 32 + ni * 8 + (lane & 3) * 2;
#pragma unroll
                for (int hf = 0; hf < 2; hf++) {
                    int m = m0 + wm * 32 + mi * 16 + (lane >> 2) + hf * 8;
                    if (m < NN)
                        *reinterpret_cast<__half2*>(outb + (size_t)m * NN + c) =
                            __floats2half2_rn(acc[mi][ni][hf * 2], acc[mi][ni][hf * 2 + 1]);
                }
            }
    }
}

// ============================ softmax + both mixes (f16 in, f16 out) ============================
__global__ __launch_bounds__(384) void softmax_mix_kernel(const float* __restrict__ Wl,
                                                          const float* __restrict__ bl,
                                                          const float* __restrict__ Ww,
                                                          const float* __restrict__ bw) {
    __shared__ __align__(16) float sm[HH][NN];
    __shared__ float wls[HH * HH], bls[HH], wws[HH * HH], bws[HH];
    const int bm = blockIdx.x;
    const int b = bm / NN, m = bm % NN;
    const int tid = threadIdx.x, lane = tid & 31, wid = tid >> 5;

    if (tid < HH * HH) { wls[tid] = Wl[tid]; wws[tid] = Ww[tid]; }
    if (tid < HH) { bls[tid] = bl[tid]; bws[tid] = bw[tid]; }

    for (int idx = tid; idx < HH * NN / 8; idx += 384) {
        int h = idx / (NN / 8), n8 = idx - h * (NN / 8);
        uint4 v = *reinterpret_cast<const uint4*>(
            g_attnf + ((size_t)(b * HH + h) * NN + m) * NN + n8 * 8);
        const __half2* hp = reinterpret_cast<const __half2*>(&v);
#pragma unroll
        for (int j = 0; j < 4; j++) {
            float2 f = __half22float2(hp[j]);
            sm[h][n8 * 8 + j * 2] = f.x;
            sm[h][n8 * 8 + j * 2 + 1] = f.y;
        }
    }
    __syncthreads();

    for (int n = tid; n < NN; n += 384) {
        float p[HH];
#pragma unroll
        for (int h = 0; h < HH; h++) p[h] = sm[h][n];
#pragma unroll
        for (int g = 0; g < HH; g++) {
            float o = bls[g];
#pragma unroll
            for (int h = 0; h < HH; h++) o += wls[g * HH + h] * p[h];
            sm[g][n] = o;
        }
    }
    __syncthreads();

    {
        const int h = wid;
        float mx = -1e30f;
        for (int n = lane; n < NN; n += 32) mx = fmaxf(mx, sm[h][n]);
#pragma unroll
        for (int o = 16; o > 0; o >>= 1) mx = fmaxf(mx, __shfl_xor_sync(0xffffffffu, mx, o));
        float sum = 0.f;
        for (int n = lane; n < NN; n += 32) {
            float e = __expf(sm[h][n] - mx);
            sm[h][n] = e; sum += e;
        }
#pragma unroll
        for (int o = 16; o > 0; o >>= 1) sum += __shfl_xor_sync(0xffffffffu, sum, o);
        float inv = 1.f / sum;
        for (int n = lane; n < NN; n += 32) sm[h][n] *= inv;
    }
    __syncthreads();

    for (int n2 = tid; n2 < NN / 2; n2 += 384) {
        int n = n2 * 2;
        float p0[HH], p1[HH];
#pragma unroll
        for (int h = 0; h < HH; h++) { p0[h] = sm[h][n]; p1[h] = sm[h][n + 1]; }
#pragma unroll
        for (int g = 0; g < HH; g++) {
            float o0 = bws[g], o1 = bws[g];
#pragma unroll
            for (int h = 0; h < HH; h++) { o0 += wws[g * HH + h] * p0[h]; o1 += wws[g * HH + h] * p1[h]; }
            size_t idx = ((size_t)(b * HH + g) * NN + m) * NN + n;
            *reinterpret_cast<__half2*>(g_a2f + idx) = __floats2half2_rn(o0, o1);
        }
    }
}

// ============================ O = attn2 @ V per (b,h)  (f16 1-MMA, BK=64) ============================
// grid (5, 192). K = 576 -> 9 BK=64 tiles.
__global__ __launch_bounds__(256, 2) void av_mma() {
    extern __shared__ char smem[];
    u32 sb = smem_u32(smem);
    const int m0 = blockIdx.x * 128, bh = blockIdx.y;
    float acc[2][4][4];
#pragma unroll
    for (int i = 0; i < 2; i++)
#pragma unroll
        for (int j = 0; j < 4; j++)
#pragma unroll
            for (int k = 0; k < 4; k++) acc[i][j][k] = 0.f;
    const size_t ab = (size_t)bh * NN * NN + (size_t)m0 * NN;
    const size_t bb = (size_t)bh * HDIM * NN;
    gemm_core_f16s64<128, 64, 4, 2>(g_a2f + ab, NN, g_vtf + bb, NN, NN, sb, acc);
    const int tid = threadIdx.x, lane = tid & 31, wid = tid >> 5;
    const int wm = wid >> 1, wn = wid & 1;
    const int b = bh / HH, h = bh - b * HH;
#pragma unroll
    for (int mi = 0; mi < 2; mi++)
#pragma unroll
        for (int ni = 0; ni < 4; ni++) {
            int dc = wn * 32 + ni * 8 + (lane & 3) * 2;
#pragma unroll
            for (int hf = 0; hf < 2; hf++) {
                int m = m0 + wm * 32 + mi * 16 + (lane >> 2) + hf * 8;
                if (m < NN) {
                    size_t base = ((size_t)b * NN + m) * CC + h * HDIM + dc;
                    *reinterpret_cast<__half2*>(g_o1f + base) =
                        __floats2half2_rn(acc[mi][ni][hf * 2], acc[mi][ni][hf * 2 + 1]);
                }
            }
        }
}

// ============================ out = o1 @ Wproj^T + bias (f16 1-MMA, BN=128, BK=64) ================
// grid (6, 72)
__global__ __launch_bounds__(256, 2) void proj_mma(const float* __restrict__ bias,
                                                   float* __restrict__ out) {
    extern __shared__ char smem[];
    u32 sb = smem_u32(smem);
    const int n0 = blockIdx.x * 128, m0 = blockIdx.y * 128;
    float acc[4][4][4];
#pragma unroll
    for (int i = 0; i < 4; i++)
#pragma unroll
        for (int j = 0; j < 4; j++)
#pragma unroll
            for (int k = 0; k < 4; k++) acc[i][j][k] = 0.f;
    gemm_core_f16s64<128, 128, 2, 4>(g_o1f + (size_t)m0 * CC, CC,
                                     g_wpf + (size_t)n0 * CC, CC, CC, sb, acc);
    const int tid = threadIdx.x, lane = tid & 31, wid = tid >> 5;
    const int wm = wid >> 2, wn = wid & 3;
#pragma unroll
    for (int mi = 0; mi < 4; mi++)
#pragma unroll
        for (int ni = 0; ni < 4; ni++) {
            int c = n0 + wn * 32 + ni * 8 + (lane & 3) * 2;
            float b0 = __ldg(&bias[c]), b1 = __ldg(&bias[c + 1]);
#pragma unroll
            for (int hf = 0; hf < 2; hf++) {
                int m = m0 + wm * 64 + mi * 16 + (lane >> 2) + hf * 8;
                *reinterpret_cast<float2*>(out + (size_t)m * CC + c) =
                    make_float2(acc[mi][ni][hf * 2] + b0, acc[mi][ni][hf * 2 + 1] + b1);
            }
        }
}

// ============================ launch ============================
extern "C" void kernel_launch(void* const* d_in, const int* in_sizes, int n_in,
                              void* d_out, int out_size) {
    const float* x     = (const float*)d_in[0];
    const float* Wqkv  = (const float*)d_in[1];
    const float* Wl    = (const float*)d_in[2];
    const float* bl    = (const float*)d_in[3];
    const float* Ww    = (const float*)d_in[4];
    const float* bw    = (const float*)d_in[5];
    const float* Wproj = (const float*)d_in[6];
    const float* bproj = (const float*)d_in[7];
    float* out = (float*)d_out;

    static bool attr_done = false;
    if (!attr_done) {
        cudaFuncSetAttribute(qkv_mma,   cudaFuncAttributeMaxDynamicSharedMemorySize, QKV_SMEM);
        cudaFuncSetAttribute(score_mma, cudaFuncAttributeMaxDynamicSharedMemorySize, SCORE_SMEM);
        cudaFuncSetAttribute(av_mma,    cudaFuncAttributeMaxDynamicSharedMemorySize, AV_SMEM);
        cudaFuncSetAttribute(proj_mma,  cudaFuncAttributeMaxDynamicSharedMemorySize, PROJ_SMEM);
        attr_done = true;
    }

    __half *xf, *wqf, *wpf;
    cudaGetSymbolAddress((void**)&xf, g_xf);
    cudaGetSymbolAddress((void**)&wqf, g_wqf);
    cudaGetSymbolAddress((void**)&wpf, g_wpf);

    const int total_q = NXQ + NWQQ + NWPQ;
    split_all_kernel<<<(total_q + 255) / 256, 256>>>(x, Wqkv, Wproj, xf, wqf, wpf);

    qkv_mma<<<dim3(18, 72), 256, QKV_SMEM>>>();
    transpose_v<<<dim3(18, 2, BB * HH), dim3(32, 8)>>>();
    score_mma<<<dim3(5, BB * HH), 256, SCORE_SMEM>>>();
    softmax_mix_kernel<<<MTOT, 384>>>(Wl, bl, Ww, bw);
    av_mma<<<dim3(5, BB * HH), 256, AV_SMEM>>>();
    proj_mma<<<dim3(6, 72), 256, PROJ_SMEM>>>(bproj, out);
}